// round 6
// baseline (speedup 1.0000x reference)
#include <cuda_runtime.h>

#define TT   512
#define BB   64
#define HH   512
#define G4   2048
#define MS   300
#define INW  812
#define NBLK 128

// ---------------- device scratch ----------------
__device__ float d_Xp[2][TT * BB][G4];      // x-projection + biases (537 MB)
__device__ float d_hbuf[2][2][BB][HH];      // [dir][parity][b][h]
__device__ float d_expl[2][MS][BB];         // unnormalized exp(logits), slot-major
__device__ float d_mem[2][BB][MS];
__device__ unsigned d_barcnt;

__global__ void reset_kernel() { d_barcnt = 0u; }

// ---------------- precompute: Xp = x @ Wx^T + b_ih + b_hh ----------------
__global__ void __launch_bounds__(256, 2) xproj_kernel(
    const float* __restrict__ seqs,
    const float* __restrict__ Wih_f, const float* __restrict__ Wih_b,
    const float* __restrict__ bih_f, const float* __restrict__ bhh_f,
    const float* __restrict__ bih_b, const float* __restrict__ bhh_b)
{
    const int d = blockIdx.z;
    const float* W  = d ? Wih_b : Wih_f;
    const float* bi = d ? bih_b : bih_f;
    const float* bh = d ? bhh_b : bhh_f;
    const int n0 = blockIdx.x * 128;
    const int m0 = blockIdx.y * 128;

    __shared__ float As[8][136];
    __shared__ float Bs[8][136];

    const int tid  = threadIdx.x;
    const int lrow = tid >> 1;
    const int kseg = (tid & 1) * 4;

    const int grow = m0 + lrow;
    const int tt   = grow >> 6;
    const int bb   = grow & 63;
    const int tsrc = d ? (TT - 1 - tt) : tt;
    const float* aptr = seqs + ((size_t)bb * TT + tsrc) * HH + kseg;
    const float* bptr = W + (size_t)(n0 + lrow) * INW + kseg;

    float acc[8][8];
#pragma unroll
    for (int r = 0; r < 8; ++r)
#pragma unroll
        for (int c = 0; c < 8; ++c) acc[r][c] = 0.0f;

    const int ty = tid >> 4;
    const int tx = tid & 15;

    for (int k0 = 0; k0 < 512; k0 += 8) {
        float4 av = *(const float4*)(aptr + k0);
        float4 bv = *(const float4*)(bptr + k0);
        __syncthreads();
        As[kseg + 0][lrow] = av.x; As[kseg + 1][lrow] = av.y;
        As[kseg + 2][lrow] = av.z; As[kseg + 3][lrow] = av.w;
        Bs[kseg + 0][lrow] = bv.x; Bs[kseg + 1][lrow] = bv.y;
        Bs[kseg + 2][lrow] = bv.z; Bs[kseg + 3][lrow] = bv.w;
        __syncthreads();
#pragma unroll
        for (int kk = 0; kk < 8; ++kk) {
            float a[8], b[8];
            *(float4*)&a[0] = *(const float4*)&As[kk][ty * 8];
            *(float4*)&a[4] = *(const float4*)&As[kk][ty * 8 + 4];
            *(float4*)&b[0] = *(const float4*)&Bs[kk][tx * 8];
            *(float4*)&b[4] = *(const float4*)&Bs[kk][tx * 8 + 4];
#pragma unroll
            for (int r = 0; r < 8; ++r)
#pragma unroll
                for (int c = 0; c < 8; ++c) acc[r][c] += a[r] * b[c];
        }
    }

    float bias[8];
#pragma unroll
    for (int c = 0; c < 8; ++c) {
        int col = n0 + tx * 8 + c;
        bias[c] = bi[col] + bh[col];
    }
#pragma unroll
    for (int r = 0; r < 8; ++r) {
        float* dst = &d_Xp[d][m0 + ty * 8 + r][n0 + tx * 8];
#pragma unroll
        for (int c = 0; c < 8; ++c) dst[c] = acc[r][c] + bias[c];
    }
}

// ---------------- grid barrier (nanosleep backoff spin) ----------------
__device__ __forceinline__ void gridbar() {
    __threadfence();
    __syncthreads();
    if (threadIdx.x == 0) {
        unsigned t = atomicAdd(&d_barcnt, 1u);
        unsigned target = (t / NBLK + 1u) * NBLK;
        while (*(volatile unsigned*)&d_barcnt < target) {
            __nanosleep(64);
        }
    }
    __syncthreads();
    __threadfence();
}

// ---------------- persistent recurrence ----------------
__global__ void __launch_bounds__(256, 1) rnn_persist(
    const float* __restrict__ Whh_f, const float* __restrict__ Whh_b,
    const float* __restrict__ Wih_f, const float* __restrict__ Wih_b,
    const float* __restrict__ Mk_f,  const float* __restrict__ Mk_b,
    const float* __restrict__ Mv_f,  const float* __restrict__ Mv_b,
    const int* __restrict__ lens,
    float* __restrict__ out)
{
    extern __shared__ float expl_s[];       // [300][68]  81600 B
    __shared__ float c_s[512];
    __shared__ float S_s[64];
    __shared__ float g_s[64 * 36];
    __shared__ float inp_s[16 * 68];
    __shared__ float w_s[16 * 36];

    const int blk = blockIdx.x;
    const int d   = blk >> 6;
    const int j   = blk & 63;
    const float* Whh = d ? Whh_b : Whh_f;
    const float* Wih = d ? Wih_b : Wih_f;
    const float* Mk  = d ? Mk_b : Mk_f;
    const float* Mv  = d ? Mv_b : Mv_f;

    const int tid  = threadIdx.x;
    const int w    = tid >> 5;
    const int lane = tid & 31;
    const int ty   = tid >> 5;
    const int tx   = tid & 31;
    const int gate = tx >> 3;
    const int u    = tx & 7;

    const int s0 = (j * MS) >> 6, s1 = ((j + 1) * MS) >> 6;
    const int m0 = s0, m1 = s1;

    for (int i = tid; i < 512; i += 256) c_s[i] = 0.0f;
    __syncthreads();

    for (int t = 0; t < TT; ++t) {
        const int rp = t & 1, wp = rp ^ 1;

        if (t > 0) {
            // ---- Phase A: expl[s][b] = exp(h[b] . Mk[s]) ----
            if (w < s1 - s0) {
                int s = s0 + w;
                const float4* mk = (const float4*)(Mk + (size_t)s * HH);
                float4 mv0 = mk[lane], mv1 = mk[lane + 32];
                float4 mv2 = mk[lane + 64], mv3 = mk[lane + 96];
                const float* hb = &d_hbuf[d][rp][0][0];
                for (int b = 0; b < BB; ++b) {
                    const float4* hr = (const float4*)(hb + (size_t)b * HH);
                    float4 h0 = __ldcg(hr + lane), h1 = __ldcg(hr + lane + 32);
                    float4 h2 = __ldcg(hr + lane + 64), h3 = __ldcg(hr + lane + 96);
                    float p = h0.x*mv0.x + h0.y*mv0.y + h0.z*mv0.z + h0.w*mv0.w
                            + h1.x*mv1.x + h1.y*mv1.y + h1.z*mv1.z + h1.w*mv1.w
                            + h2.x*mv2.x + h2.y*mv2.y + h2.z*mv2.z + h2.w*mv2.w
                            + h3.x*mv3.x + h3.y*mv3.y + h3.z*mv3.z + h3.w*mv3.w;
                    p += __shfl_xor_sync(0xffffffffu, p, 16);
                    p += __shfl_xor_sync(0xffffffffu, p, 8);
                    p += __shfl_xor_sync(0xffffffffu, p, 4);
                    p += __shfl_xor_sync(0xffffffffu, p, 2);
                    p += __shfl_xor_sync(0xffffffffu, p, 1);
                    if (lane == 0) d_expl[d][s][b] = __expf(p);
                }
            }
            gridbar();

            // ---- Phase B: softmax-normalize + mem = alpha @ Mv^T ----
            for (int idx = tid; idx < MS * BB; idx += 256) {
                int s = idx >> 6, b = idx & 63;
                expl_s[s * 68 + b] = __ldcg(&d_expl[d][s][b]);
            }
            __syncthreads();
            {
                int b = tid >> 2, q = tid & 3;
                float ps = 0.0f;
                for (int s = q * 75; s < q * 75 + 75; ++s) ps += expl_s[s * 68 + b];
                ps += __shfl_xor_sync(0xffffffffu, ps, 1);
                ps += __shfl_xor_sync(0xffffffffu, ps, 2);
                if (q == 0) S_s[b] = ps;
            }
            __syncthreads();
            {
                int b = tid >> 2, q = tid & 3;
                for (int m = m0; m < m1; ++m) {
                    const float* mvrow = Mv + (size_t)m * MS;
                    float acc = 0.0f;
                    for (int s = q * 75; s < q * 75 + 75; ++s)
                        acc += expl_s[s * 68 + b] * __ldg(mvrow + s);
                    acc += __shfl_xor_sync(0xffffffffu, acc, 1);
                    acc += __shfl_xor_sync(0xffffffffu, acc, 2);
                    if (q == 0) d_mem[d][b][m] = acc / S_s[b];
                }
            }
            gridbar();
        }

        // ---- Phase D: gates = Xp + mem@Wm^T + h@Whh^T ; cell ----
        float acc[8];
        {
            const float* xp = &d_Xp[d][(size_t)t * BB][0];
            const int col = gate * 512 + j * 8 + u;
#pragma unroll
            for (int r = 0; r < 8; ++r)
                acc[r] = __ldcs(xp + (size_t)(ty * 8 + r) * G4 + col);
        }

        if (t > 0) {
            // mem part: K = 300
            const float* inp = &d_mem[d][0][0];
            for (int k0 = 0; k0 < MS; k0 += 16) {
                __syncthreads();
                {
                    int kk = tid & 15, k = k0 + kk;
#pragma unroll
                    for (int i = 0; i < 4; ++i) {
                        int b = (tid >> 4) + i * 16;
                        inp_s[kk * 68 + b] = (k < MS) ? __ldcg(inp + (size_t)b * MS + k) : 0.0f;
                    }
#pragma unroll
                    for (int i = 0; i < 2; ++i) {
                        int x = (tid >> 4) + i * 16;
                        int row = (x >> 3) * 512 + j * 8 + (x & 7);
                        w_s[kk * 36 + x] = (k < MS) ? __ldg(Wih + (size_t)row * INW + 512 + k) : 0.0f;
                    }
                }
                __syncthreads();
#pragma unroll
                for (int kk = 0; kk < 16; ++kk) {
                    float wv = w_s[kk * 36 + tx];
                    float4 a0 = *(const float4*)&inp_s[kk * 68 + ty * 8];
                    float4 a1 = *(const float4*)&inp_s[kk * 68 + ty * 8 + 4];
                    acc[0] += a0.x * wv; acc[1] += a0.y * wv;
                    acc[2] += a0.z * wv; acc[3] += a0.w * wv;
                    acc[4] += a1.x * wv; acc[5] += a1.y * wv;
                    acc[6] += a1.z * wv; acc[7] += a1.w * wv;
                }
            }
            // h part: K = 512
            const float* inp2 = &d_hbuf[d][rp][0][0];
            for (int k0 = 0; k0 < HH; k0 += 16) {
                __syncthreads();
                {
                    int kk = tid & 15, k = k0 + kk;
#pragma unroll
                    for (int i = 0; i < 4; ++i) {
                        int b = (tid >> 4) + i * 16;
                        inp_s[kk * 68 + b] = __ldcg(inp2 + (size_t)b * HH + k);
                    }
#pragma unroll
                    for (int i = 0; i < 2; ++i) {
                        int x = (tid >> 4) + i * 16;
                        int row = (x >> 3) * 512 + j * 8 + (x & 7);
                        w_s[kk * 36 + x] = __ldg(Whh + (size_t)row * HH + k);
                    }
                }
                __syncthreads();
#pragma unroll
                for (int kk = 0; kk < 16; ++kk) {
                    float wv = w_s[kk * 36 + tx];
                    float4 a0 = *(const float4*)&inp_s[kk * 68 + ty * 8];
                    float4 a1 = *(const float4*)&inp_s[kk * 68 + ty * 8 + 4];
                    acc[0] += a0.x * wv; acc[1] += a0.y * wv;
                    acc[2] += a0.z * wv; acc[3] += a0.w * wv;
                    acc[4] += a1.x * wv; acc[5] += a1.y * wv;
                    acc[6] += a1.z * wv; acc[7] += a1.w * wv;
                }
            }
        }

        __syncthreads();
#pragma unroll
        for (int r = 0; r < 8; ++r) g_s[(ty * 8 + r) * 36 + tx] = acc[r];
        __syncthreads();

#pragma unroll
        for (int pi = 0; pi < 2; ++pi) {
            int p = tid + pi * 256;
            int b = p >> 3, uu = p & 7;
            float gi = g_s[b * 36 + uu];
            float gf = g_s[b * 36 + 8 + uu];
            float gg = g_s[b * 36 + 16 + uu];
            float go = g_s[b * 36 + 24 + uu];
            float iv = 1.0f / (1.0f + __expf(-gi));
            float fv = 1.0f / (1.0f + __expf(-gf));
            float gv = tanhf(gg);
            float ov = 1.0f / (1.0f + __expf(-go));
            float c = fv * c_s[p] + iv * gv;
            c_s[p] = c;
            float h = ov * tanhf(c);
            d_hbuf[d][wp][b][j * 8 + uu] = h;
            int torig = d ? (TT - 1 - t) : t;
            float mval = (torig < lens[b]) ? h : 0.0f;
            out[((size_t)b * TT + torig) * 1024 + d * 512 + j * 8 + uu] = mval;
        }
        gridbar();
    }
}

// ---------------- launch ----------------
extern "C" void kernel_launch(void* const* d_in, const int* in_sizes, int n_in,
                              void* d_out, int out_size) {
    const float* seqs   = (const float*)d_in[0];
    const int*   ln     = (const int*)d_in[1];     // int32 (JAX x64 disabled)
    const float* Wih_f  = (const float*)d_in[2];
    const float* Whh_f  = (const float*)d_in[3];
    const float* bih_f  = (const float*)d_in[4];
    const float* bhh_f  = (const float*)d_in[5];
    const float* Mk_f   = (const float*)d_in[6];
    const float* Mv_f   = (const float*)d_in[7];
    const float* Wih_b  = (const float*)d_in[8];
    const float* Whh_b  = (const float*)d_in[9];
    const float* bih_b  = (const float*)d_in[10];
    const float* bhh_b  = (const float*)d_in[11];
    const float* Mk_b   = (const float*)d_in[12];
    const float* Mv_b   = (const float*)d_in[13];
    float* out = (float*)d_out;

    cudaFuncSetAttribute(rnn_persist,
                         cudaFuncAttributeMaxDynamicSharedMemorySize, 81600);

    reset_kernel<<<1, 1>>>();
    xproj_kernel<<<dim3(16, 256, 2), 256>>>(seqs, Wih_f, Wih_b,
                                            bih_f, bhh_f, bih_b, bhh_b);
    rnn_persist<<<NBLK, 256, 81600>>>(Whh_f, Whh_b, Wih_f, Wih_b,
                                      Mk_f, Mk_b, Mv_f, Mv_b, ln, out);
}

// round 7
// speedup vs baseline: 1.7841x; 1.7841x over previous
#include <cuda_runtime.h>

#define TT   512
#define BB   64
#define HH   512
#define G4   2048
#define MS   300
#define INW  812
#define NBLK 128
#define BQ_F 33280              /* 832*40 floats: resident weight smem  */
#define ACH  4352               /* 64*68 floats per A chunk buffer      */
#define DYN_BYTES ((BQ_F + 2*ACH)*4)

// ---------------- device scratch ----------------
__device__ float d_Xp[2][TT * BB][G4];
__device__ float d_hbuf[2][2][BB][HH];
__device__ float d_expl[2][MS][BB];
__device__ float d_part[2][64][BB];
__device__ float d_Pt[2][G4][320];      // P[col][s] = sum_m Wm[col][m]*Mv[m][s]
__device__ unsigned d_barcnt;

__global__ void reset_kernel() { d_barcnt = 0u; }

__device__ __forceinline__ float f2tf(float f) {
    unsigned u; asm("cvt.rna.tf32.f32 %0, %1;" : "=r"(u) : "f"(f));
    return __uint_as_float(u);
}
__device__ __forceinline__ void mma8(float* d, unsigned a0, unsigned a1,
    unsigned a2, unsigned a3, unsigned b0, unsigned b1) {
    asm volatile("mma.sync.aligned.m16n8k8.row.col.f32.tf32.tf32.f32 "
        "{%0,%1,%2,%3},{%4,%5,%6,%7},{%8,%9},{%0,%1,%2,%3};"
        : "+f"(d[0]), "+f"(d[1]), "+f"(d[2]), "+f"(d[3])
        : "r"(a0), "r"(a1), "r"(a2), "r"(a3), "r"(b0), "r"(b1));
}

// ---------------- xproj: Xp = x @ Wx^T + b_ih + b_hh (fp32, unchanged) ------
__global__ void __launch_bounds__(256, 2) xproj_kernel(
    const float* __restrict__ seqs,
    const float* __restrict__ Wih_f, const float* __restrict__ Wih_b,
    const float* __restrict__ bih_f, const float* __restrict__ bhh_f,
    const float* __restrict__ bih_b, const float* __restrict__ bhh_b)
{
    const int d = blockIdx.z;
    const float* W  = d ? Wih_b : Wih_f;
    const float* bi = d ? bih_b : bih_f;
    const float* bh = d ? bhh_b : bhh_f;
    const int n0 = blockIdx.x * 128;
    const int m0 = blockIdx.y * 128;

    __shared__ float As[8][136];
    __shared__ float Bs[8][136];

    const int tid  = threadIdx.x;
    const int lrow = tid >> 1;
    const int kseg = (tid & 1) * 4;

    const int grow = m0 + lrow;
    const int tt   = grow >> 6;
    const int bb   = grow & 63;
    const int tsrc = d ? (TT - 1 - tt) : tt;
    const float* aptr = seqs + ((size_t)bb * TT + tsrc) * HH + kseg;
    const float* bptr = W + (size_t)(n0 + lrow) * INW + kseg;

    float acc[8][8];
#pragma unroll
    for (int r = 0; r < 8; ++r)
#pragma unroll
        for (int c = 0; c < 8; ++c) acc[r][c] = 0.0f;

    const int ty = tid >> 4;
    const int tx = tid & 15;

    for (int k0 = 0; k0 < 512; k0 += 8) {
        float4 av = *(const float4*)(aptr + k0);
        float4 bv = *(const float4*)(bptr + k0);
        __syncthreads();
        As[kseg + 0][lrow] = av.x; As[kseg + 1][lrow] = av.y;
        As[kseg + 2][lrow] = av.z; As[kseg + 3][lrow] = av.w;
        Bs[kseg + 0][lrow] = bv.x; Bs[kseg + 1][lrow] = bv.y;
        Bs[kseg + 2][lrow] = bv.z; Bs[kseg + 3][lrow] = bv.w;
        __syncthreads();
#pragma unroll
        for (int kk = 0; kk < 8; ++kk) {
            float a[8], b[8];
            *(float4*)&a[0] = *(const float4*)&As[kk][ty * 8];
            *(float4*)&a[4] = *(const float4*)&As[kk][ty * 8 + 4];
            *(float4*)&b[0] = *(const float4*)&Bs[kk][tx * 8];
            *(float4*)&b[4] = *(const float4*)&Bs[kk][tx * 8 + 4];
#pragma unroll
            for (int r = 0; r < 8; ++r)
#pragma unroll
                for (int c = 0; c < 8; ++c) acc[r][c] += a[r] * b[c];
        }
    }

    float bias[8];
#pragma unroll
    for (int c = 0; c < 8; ++c) {
        int col = n0 + tx * 8 + c;
        bias[c] = bi[col] + bh[col];
    }
#pragma unroll
    for (int r = 0; r < 8; ++r) {
        float* dst = &d_Xp[d][m0 + ty * 8 + r][n0 + tx * 8];
#pragma unroll
        for (int c = 0; c < 8; ++c) dst[c] = acc[r][c] + bias[c];
    }
}

// ---------------- Pt precompute (fp32, 64x64 tiles) ----------------
__global__ void __launch_bounds__(256, 2) p_kernel(
    const float* __restrict__ Wih_f, const float* __restrict__ Wih_b,
    const float* __restrict__ Mv_f,  const float* __restrict__ Mv_b)
{
    const int d = blockIdx.z;
    const float* W  = d ? Wih_b : Wih_f;
    const float* Mv = d ? Mv_b : Mv_f;
    const int n0 = blockIdx.x * 64;       // s
    const int m0 = blockIdx.y * 64;       // col

    __shared__ float As[8][68], Bs[8][68];
    const int tid = threadIdx.x;
    const int ty = tid >> 4, tx = tid & 15;

    float acc[4][4];
#pragma unroll
    for (int r = 0; r < 4; ++r)
#pragma unroll
        for (int c = 0; c < 4; ++c) acc[r][c] = 0.0f;

    for (int k0 = 0; k0 < 304; k0 += 8) {
        __syncthreads();
#pragma unroll
        for (int i = 0; i < 2; ++i) {
            int idx = i * 256 + tid;
            int r = idx & 63, kk = idx >> 6;
            int k = k0 + kk;
            As[kk][r] = (k < MS) ? W[(size_t)(m0 + r) * INW + 512 + k] : 0.0f;
            Bs[kk][r] = (k < MS && n0 + r < MS) ? Mv[(size_t)k * MS + n0 + r] : 0.0f;
        }
        __syncthreads();
#pragma unroll
        for (int kk = 0; kk < 8; ++kk) {
            float a[4], b[4];
#pragma unroll
            for (int r = 0; r < 4; ++r) a[r] = As[kk][ty * 4 + r];
#pragma unroll
            for (int c = 0; c < 4; ++c) b[c] = Bs[kk][tx * 4 + c];
#pragma unroll
            for (int r = 0; r < 4; ++r)
#pragma unroll
                for (int c = 0; c < 4; ++c) acc[r][c] += a[r] * b[c];
        }
    }
#pragma unroll
    for (int r = 0; r < 4; ++r)
#pragma unroll
        for (int c = 0; c < 4; ++c)
            d_Pt[d][m0 + ty * 4 + r][n0 + tx * 4 + c] = acc[r][c];
}

// ---------------- grid barrier ----------------
__device__ __forceinline__ void gridbar() {
    __threadfence();
    __syncthreads();
    if (threadIdx.x == 0) {
        unsigned t = atomicAdd(&d_barcnt, 1u);
        unsigned target = (t / NBLK + 1u) * NBLK;
        while (*(volatile unsigned*)&d_barcnt < target) { __nanosleep(64); }
    }
    __syncthreads();
    __threadfence();
}

// ---------------- A-chunk staging ----------------
__device__ __forceinline__ void fetch_chunk(int c, int d, int rp, int tid, float* vb) {
    if (c < 8) {
        const float* hb = &d_hbuf[d][rp][0][0];
#pragma unroll
        for (int jj = 0; jj < 4; ++jj) {
            int idx = jj * 256 + tid;
            int b = idx >> 4, kq = idx & 15;
            float4 v = __ldcg((const float4*)(hb + b * HH + c * 64 + kq * 4));
            vb[jj*4+0] = v.x; vb[jj*4+1] = v.y; vb[jj*4+2] = v.z; vb[jj*4+3] = v.w;
        }
    } else {
#pragma unroll
        for (int jj = 0; jj < 16; ++jj) {
            int idx = jj * 256 + tid;
            int sl = idx >> 6, b = idx & 63;
            int s = (c - 8) * 64 + sl;
            vb[jj] = (s < MS) ? __ldcg(&d_expl[d][s][b]) : 0.0f;
        }
    }
}
__device__ __forceinline__ void store_chunk(int c, int tid, const float* vb, float* A) {
    if (c < 8) {
#pragma unroll
        for (int jj = 0; jj < 4; ++jj) {
            int idx = jj * 256 + tid;
            int b = idx >> 4, kq = idx & 15;
            float4 sv;
            sv.x = f2tf(vb[jj*4+0]); sv.y = f2tf(vb[jj*4+1]);
            sv.z = f2tf(vb[jj*4+2]); sv.w = f2tf(vb[jj*4+3]);
            *(float4*)(A + b * 68 + kq * 4) = sv;
        }
    } else {
#pragma unroll
        for (int jj = 0; jj < 16; ++jj) {
            int idx = jj * 256 + tid;
            int sl = idx >> 6, b = idx & 63;
            A[b * 68 + sl] = f2tf(vb[jj]);
        }
    }
}

__device__ __forceinline__ void mma_chunk(const float* A, const float* Bq, int c,
    float* d0, float* d1, int am, int t4, int g0, int gid)
{
#pragma unroll
    for (int ks = 0; ks < 8; ++ks) {
        int ka = ks * 8 + t4;
        unsigned a0 = __float_as_uint(A[am + ka]);
        unsigned a1 = __float_as_uint(A[am + 8 * 68 + ka]);
        unsigned a2 = __float_as_uint(A[am + ka + 4]);
        unsigned a3 = __float_as_uint(A[am + 8 * 68 + ka + 4]);
        const float* B0 = Bq + (c * 64 + ks * 8 + t4) * 40;
        unsigned b0 = __float_as_uint(B0[g0 * 8 + gid]);
        unsigned b1 = __float_as_uint(B0[160 + g0 * 8 + gid]);
        mma8(d0, a0, a1, a2, a3, b0, b1);
        unsigned b2 = __float_as_uint(B0[(g0 + 1) * 8 + gid]);
        unsigned b3 = __float_as_uint(B0[160 + (g0 + 1) * 8 + gid]);
        mma8(d1, a0, a1, a2, a3, b2, b3);
    }
}

// ---------------- persistent recurrence ----------------
__global__ void __launch_bounds__(256, 1) rnn_persist(
    const float* __restrict__ Whh_f, const float* __restrict__ Whh_b,
    const float* __restrict__ Mk_f,  const float* __restrict__ Mk_b,
    const int* __restrict__ lens,
    float* __restrict__ out)
{
    extern __shared__ float shm[];          // Bq[832*40] + 2 A chunk buffers
    __shared__ float c_s[512];
    __shared__ float S_s[64];
    __shared__ float g_s[64 * 33];
    __shared__ float e_s[8 * 64];

    const int blk = blockIdx.x;
    const int d   = blk >> 6;
    const int j   = blk & 63;
    const float* Whh = d ? Whh_b : Whh_f;
    const float* Mk  = d ? Mk_b : Mk_f;

    const int tid  = threadIdx.x;
    const int w    = tid >> 5;
    const int lane = tid & 31;
    const int gid  = lane >> 2, t4 = lane & 3;
    const int mtile = w & 3, g0 = (w >> 2) * 2;
    const int row0 = mtile * 16 + gid, row1 = row0 + 8;
    const int am   = row0 * 68;

    const int s0 = (j * MS) >> 6, s1 = ((j + 1) * MS) >> 6;
    const int scnt = s1 - s0;

    // one-time: pack resident B (Whh slice + Pt slice) to tf32
    for (int idx = tid; idx < 832 * 32; idx += 256) {
        int k = idx >> 5, n = idx & 31;
        int ncol = (n >> 3) * 512 + j * 8 + (n & 7);
        float v = (k < 512) ? Whh[(size_t)ncol * HH + k] : d_Pt[d][ncol][k - 512];
        shm[k * 40 + n] = f2tf(v);
    }
    for (int i = tid; i < 512; i += 256) c_s[i] = 0.0f;
    __syncthreads();

    for (int t = 0; t < TT; ++t) {
        const int rp = t & 1, wp = rp ^ 1;

        if (t > 0) {
            // ---- Phase A: expl + per-block partial sums ----
            if (w < scnt) {
                int s = s0 + w;
                const float4* mk = (const float4*)(Mk + (size_t)s * HH);
                float4 mv0 = mk[lane], mv1 = mk[lane + 32];
                float4 mv2 = mk[lane + 64], mv3 = mk[lane + 96];
                const float* hb = &d_hbuf[d][rp][0][0];
                for (int b = 0; b < BB; ++b) {
                    const float4* hr = (const float4*)(hb + (size_t)b * HH);
                    float4 h0 = __ldcg(hr + lane), h1 = __ldcg(hr + lane + 32);
                    float4 h2 = __ldcg(hr + lane + 64), h3 = __ldcg(hr + lane + 96);
                    float p = h0.x*mv0.x + h0.y*mv0.y + h0.z*mv0.z + h0.w*mv0.w
                            + h1.x*mv1.x + h1.y*mv1.y + h1.z*mv1.z + h1.w*mv1.w
                            + h2.x*mv2.x + h2.y*mv2.y + h2.z*mv2.z + h2.w*mv2.w
                            + h3.x*mv3.x + h3.y*mv3.y + h3.z*mv3.z + h3.w*mv3.w;
                    p += __shfl_xor_sync(0xffffffffu, p, 16);
                    p += __shfl_xor_sync(0xffffffffu, p, 8);
                    p += __shfl_xor_sync(0xffffffffu, p, 4);
                    p += __shfl_xor_sync(0xffffffffu, p, 2);
                    p += __shfl_xor_sync(0xffffffffu, p, 1);
                    if (lane == 0) {
                        float e = __expf(p);
                        d_expl[d][s][b] = e;
                        e_s[w * 64 + b] = e;
                    }
                }
            }
            __syncthreads();
            if (tid < 64) {
                float ps = 0.0f;
                for (int ww = 0; ww < scnt; ++ww) ps += e_s[ww * 64 + tid];
                d_part[d][j][tid] = ps;
            }
            gridbar();
        }

        // ---- Phase D: gates = Xp + h@Whh^T + (expl@P)/S ----
        float aG0[4], aG1[4];
        {
            const float* xp = &d_Xp[d][(size_t)t * BB][0];
            int cA = g0 * 512 + j * 8 + 2 * t4;
            float2 v;
            v = __ldcs((const float2*)(xp + (size_t)row0 * G4 + cA));
            aG0[0] = v.x; aG0[1] = v.y;
            v = __ldcs((const float2*)(xp + (size_t)row1 * G4 + cA));
            aG0[2] = v.x; aG0[3] = v.y;
            v = __ldcs((const float2*)(xp + (size_t)row0 * G4 + cA + 512));
            aG1[0] = v.x; aG1[1] = v.y;
            v = __ldcs((const float2*)(xp + (size_t)row1 * G4 + cA + 512));
            aG1[2] = v.x; aG1[3] = v.y;
        }

        if (t > 0) {
            if (tid < 64) {
                float a = 0.0f;
#pragma unroll 16
                for (int jj = 0; jj < 64; ++jj) a += __ldcg(&d_part[d][jj][tid]);
                S_s[tid] = 1.0f / a;
            }
            float aE0[4] = {0,0,0,0}, aE1[4] = {0,0,0,0};
            float vb[16];
            fetch_chunk(0, d, rp, tid, vb);
            store_chunk(0, tid, vb, shm + BQ_F);
            __syncthreads();
#pragma unroll 1
            for (int c = 0; c < 13; ++c) {
                if (c < 12) fetch_chunk(c + 1, d, rp, tid, vb);
                const float* A = shm + BQ_F + (c & 1) * ACH;
                if (c < 8) mma_chunk(A, shm, c, aG0, aG1, am, t4, g0, gid);
                else       mma_chunk(A, shm, c, aE0, aE1, am, t4, g0, gid);
                __syncthreads();
                if (c < 12) {
                    store_chunk(c + 1, tid, vb, shm + BQ_F + ((c + 1) & 1) * ACH);
                    __syncthreads();
                }
            }
            float si0 = S_s[row0], si1 = S_s[row1];
            aG0[0] += aE0[0] * si0; aG0[1] += aE0[1] * si0;
            aG0[2] += aE0[2] * si1; aG0[3] += aE0[3] * si1;
            aG1[0] += aE1[0] * si0; aG1[1] += aE1[1] * si0;
            aG1[2] += aE1[2] * si1; aG1[3] += aE1[3] * si1;
        }

        __syncthreads();
        {
            int cl0 = g0 * 8 + 2 * t4, cl1 = cl0 + 8;
            g_s[row0 * 33 + cl0] = aG0[0]; g_s[row0 * 33 + cl0 + 1] = aG0[1];
            g_s[row1 * 33 + cl0] = aG0[2]; g_s[row1 * 33 + cl0 + 1] = aG0[3];
            g_s[row0 * 33 + cl1] = aG1[0]; g_s[row0 * 33 + cl1 + 1] = aG1[1];
            g_s[row1 * 33 + cl1] = aG1[2]; g_s[row1 * 33 + cl1 + 1] = aG1[3];
        }
        __syncthreads();

#pragma unroll
        for (int pi = 0; pi < 2; ++pi) {
            int p = tid + pi * 256;
            int b = p >> 3, uu = p & 7;
            float gi = g_s[b * 33 + uu];
            float gf = g_s[b * 33 + 8 + uu];
            float gg = g_s[b * 33 + 16 + uu];
            float go = g_s[b * 33 + 24 + uu];
            float iv = 1.0f / (1.0f + __expf(-gi));
            float fv = 1.0f / (1.0f + __expf(-gf));
            float gv = tanhf(gg);
            float ov = 1.0f / (1.0f + __expf(-go));
            float c = fv * c_s[p] + iv * gv;
            c_s[p] = c;
            float h = ov * tanhf(c);
            d_hbuf[d][wp][b][j * 8 + uu] = h;
            int torig = d ? (TT - 1 - t) : t;
            float mval = (torig < lens[b]) ? h : 0.0f;
            out[((size_t)b * TT + torig) * 1024 + d * 512 + j * 8 + uu] = mval;
        }
        gridbar();
    }
}

// ---------------- launch ----------------
extern "C" void kernel_launch(void* const* d_in, const int* in_sizes, int n_in,
                              void* d_out, int out_size) {
    const float* seqs   = (const float*)d_in[0];
    const int*   ln     = (const int*)d_in[1];
    const float* Wih_f  = (const float*)d_in[2];
    const float* Whh_f  = (const float*)d_in[3];
    const float* bih_f  = (const float*)d_in[4];
    const float* bhh_f  = (const float*)d_in[5];
    const float* Mk_f   = (const float*)d_in[6];
    const float* Mv_f   = (const float*)d_in[7];
    const float* Wih_b  = (const float*)d_in[8];
    const float* Whh_b  = (const float*)d_in[9];
    const float* bih_b  = (const float*)d_in[10];
    const float* bhh_b  = (const float*)d_in[11];
    const float* Mk_b   = (const float*)d_in[12];
    const float* Mv_b   = (const float*)d_in[13];
    float* out = (float*)d_out;

    cudaFuncSetAttribute(rnn_persist,
                         cudaFuncAttributeMaxDynamicSharedMemorySize, DYN_BYTES);

    reset_kernel<<<1, 1>>>();
    xproj_kernel<<<dim3(16, 256, 2), 256>>>(seqs, Wih_f, Wih_b,
                                            bih_f, bhh_f, bih_b, bhh_b);
    p_kernel<<<dim3(5, 32, 2), 256>>>(Wih_f, Wih_b, Mv_f, Mv_b);
    rnn_persist<<<NBLK, 256, DYN_BYTES>>>(Whh_f, Whh_b, Mk_f, Mk_b, ln, out);
}

// round 8
// speedup vs baseline: 3.7632x; 2.1094x over previous
#include <cuda_runtime.h>

#define TT   512
#define BB   64
#define HH   512
#define G4   2048
#define MS   300
#define INW  812
#define NBLK 128
#define BQ_F 33280              /* 832 k x 40 n floats: resident weight smem */
#define ACH  4352               /* 64*68 floats per A chunk buffer           */
#define DYN_BYTES ((BQ_F + 2*ACH)*4)

// ---------------- device scratch ----------------
__device__ float d_Xp[2][TT * BB][G4];
__device__ float d_hbuf[2][2][BB][HH];
__device__ float d_expl[2][MS][BB];
__device__ float d_part[2][64][BB];
__device__ float d_Pt[2][G4][320];
__device__ unsigned d_barcnt;

__global__ void reset_kernel() { d_barcnt = 0u; }

__device__ __forceinline__ float f2tf(float f) {
    unsigned u; asm("cvt.rna.tf32.f32 %0, %1;" : "=r"(u) : "f"(f));
    return __uint_as_float(u);
}
__device__ __forceinline__ void mma8(float* d, unsigned a0, unsigned a1,
    unsigned a2, unsigned a3, unsigned b0, unsigned b1) {
    asm volatile("mma.sync.aligned.m16n8k8.row.col.f32.tf32.tf32.f32 "
        "{%0,%1,%2,%3},{%4,%5,%6,%7},{%8,%9},{%0,%1,%2,%3};"
        : "+f"(d[0]), "+f"(d[1]), "+f"(d[2]), "+f"(d[3])
        : "r"(a0), "r"(a1), "r"(a2), "r"(a3), "r"(b0), "r"(b1));
}

// ---------------- xproj (fp32, unchanged control) ----------------
__global__ void __launch_bounds__(256, 2) xproj_kernel(
    const float* __restrict__ seqs,
    const float* __restrict__ Wih_f, const float* __restrict__ Wih_b,
    const float* __restrict__ bih_f, const float* __restrict__ bhh_f,
    const float* __restrict__ bih_b, const float* __restrict__ bhh_b)
{
    const int d = blockIdx.z;
    const float* W  = d ? Wih_b : Wih_f;
    const float* bi = d ? bih_b : bih_f;
    const float* bh = d ? bhh_b : bhh_f;
    const int n0 = blockIdx.x * 128;
    const int m0 = blockIdx.y * 128;

    __shared__ float As[8][136];
    __shared__ float Bs[8][136];

    const int tid  = threadIdx.x;
    const int lrow = tid >> 1;
    const int kseg = (tid & 1) * 4;

    const int grow = m0 + lrow;
    const int tt   = grow >> 6;
    const int bb   = grow & 63;
    const int tsrc = d ? (TT - 1 - tt) : tt;
    const float* aptr = seqs + ((size_t)bb * TT + tsrc) * HH + kseg;
    const float* bptr = W + (size_t)(n0 + lrow) * INW + kseg;

    float acc[8][8];
#pragma unroll
    for (int r = 0; r < 8; ++r)
#pragma unroll
        for (int c = 0; c < 8; ++c) acc[r][c] = 0.0f;

    const int ty = tid >> 4;
    const int tx = tid & 15;

    for (int k0 = 0; k0 < 512; k0 += 8) {
        float4 av = *(const float4*)(aptr + k0);
        float4 bv = *(const float4*)(bptr + k0);
        __syncthreads();
        As[kseg + 0][lrow] = av.x; As[kseg + 1][lrow] = av.y;
        As[kseg + 2][lrow] = av.z; As[kseg + 3][lrow] = av.w;
        Bs[kseg + 0][lrow] = bv.x; Bs[kseg + 1][lrow] = bv.y;
        Bs[kseg + 2][lrow] = bv.z; Bs[kseg + 3][lrow] = bv.w;
        __syncthreads();
#pragma unroll
        for (int kk = 0; kk < 8; ++kk) {
            float a[8], b[8];
            *(float4*)&a[0] = *(const float4*)&As[kk][ty * 8];
            *(float4*)&a[4] = *(const float4*)&As[kk][ty * 8 + 4];
            *(float4*)&b[0] = *(const float4*)&Bs[kk][tx * 8];
            *(float4*)&b[4] = *(const float4*)&Bs[kk][tx * 8 + 4];
#pragma unroll
            for (int r = 0; r < 8; ++r)
#pragma unroll
                for (int c = 0; c < 8; ++c) acc[r][c] += a[r] * b[c];
        }
    }

    float bias[8];
#pragma unroll
    for (int c = 0; c < 8; ++c) {
        int col = n0 + tx * 8 + c;
        bias[c] = bi[col] + bh[col];
    }
#pragma unroll
    for (int r = 0; r < 8; ++r) {
        float* dst = &d_Xp[d][m0 + ty * 8 + r][n0 + tx * 8];
#pragma unroll
        for (int c = 0; c < 8; ++c) dst[c] = acc[r][c] + bias[c];
    }
}

// ---------------- Pt precompute (unchanged control) ----------------
__global__ void __launch_bounds__(256, 2) p_kernel(
    const float* __restrict__ Wih_f, const float* __restrict__ Wih_b,
    const float* __restrict__ Mv_f,  const float* __restrict__ Mv_b)
{
    const int d = blockIdx.z;
    const float* W  = d ? Wih_b : Wih_f;
    const float* Mv = d ? Mv_b : Mv_f;
    const int n0 = blockIdx.x * 64;
    const int m0 = blockIdx.y * 64;

    __shared__ float As[8][68], Bs[8][68];
    const int tid = threadIdx.x;
    const int ty = tid >> 4, tx = tid & 15;

    float acc[4][4];
#pragma unroll
    for (int r = 0; r < 4; ++r)
#pragma unroll
        for (int c = 0; c < 4; ++c) acc[r][c] = 0.0f;

    for (int k0 = 0; k0 < 304; k0 += 8) {
        __syncthreads();
#pragma unroll
        for (int i = 0; i < 2; ++i) {
            int idx = i * 256 + tid;
            int r = idx & 63, kk = idx >> 6;
            int k = k0 + kk;
            As[kk][r] = (k < MS) ? W[(size_t)(m0 + r) * INW + 512 + k] : 0.0f;
            Bs[kk][r] = (k < MS && n0 + r < MS) ? Mv[(size_t)k * MS + n0 + r] : 0.0f;
        }
        __syncthreads();
#pragma unroll
        for (int kk = 0; kk < 8; ++kk) {
            float a[4], b[4];
#pragma unroll
            for (int r = 0; r < 4; ++r) a[r] = As[kk][ty * 4 + r];
#pragma unroll
            for (int c = 0; c < 4; ++c) b[c] = Bs[kk][tx * 4 + c];
#pragma unroll
            for (int r = 0; r < 4; ++r)
#pragma unroll
                for (int c = 0; c < 4; ++c) acc[r][c] += a[r] * b[c];
        }
    }
#pragma unroll
    for (int r = 0; r < 4; ++r)
#pragma unroll
        for (int c = 0; c < 4; ++c)
            d_Pt[d][m0 + ty * 4 + r][n0 + tx * 4 + c] = acc[r][c];
}

// ---------------- grid barrier (tight spin, late backoff) ----------------
__device__ __forceinline__ void gridbar() {
    __threadfence();
    __syncthreads();
    if (threadIdx.x == 0) {
        unsigned t = atomicAdd(&d_barcnt, 1u);
        unsigned target = (t / NBLK + 1u) * NBLK;
        int spins = 0;
        while (*(volatile unsigned*)&d_barcnt < target) {
            if (++spins > 256) __nanosleep(32);
        }
    }
    __syncthreads();
    __threadfence();
}

// ---------------- A-chunk staging ----------------
__device__ __forceinline__ void fetch_chunk(int c, int d, int rp, int tid, float* vb) {
    if (c < 8) {
        const float* hb = &d_hbuf[d][rp][0][0];
#pragma unroll
        for (int jj = 0; jj < 4; ++jj) {
            int idx = jj * 256 + tid;
            int b = idx >> 4, kq = idx & 15;
            float4 v = __ldcg((const float4*)(hb + b * HH + c * 64 + kq * 4));
            vb[jj*4+0] = v.x; vb[jj*4+1] = v.y; vb[jj*4+2] = v.z; vb[jj*4+3] = v.w;
        }
    } else {
#pragma unroll
        for (int jj = 0; jj < 16; ++jj) {
            int idx = jj * 256 + tid;
            int sl = idx >> 6, b = idx & 63;
            int s = (c - 8) * 64 + sl;
            vb[jj] = (s < MS) ? __ldcg(&d_expl[d][s][b]) : 0.0f;
        }
    }
}
__device__ __forceinline__ void store_chunk(int c, int tid, const float* vb, float* A) {
    if (c < 8) {
#pragma unroll
        for (int jj = 0; jj < 4; ++jj) {
            int idx = jj * 256 + tid;
            int b = idx >> 4, kq = idx & 15;
            float4 sv;
            sv.x = f2tf(vb[jj*4+0]); sv.y = f2tf(vb[jj*4+1]);
            sv.z = f2tf(vb[jj*4+2]); sv.w = f2tf(vb[jj*4+3]);
            *(float4*)(A + b * 68 + kq * 4) = sv;
        }
    } else {
#pragma unroll
        for (int jj = 0; jj < 16; ++jj) {
            int idx = jj * 256 + tid;
            int sl = idx >> 6, b = idx & 63;
            A[b * 68 + sl] = f2tf(vb[jj]);
        }
    }
}

// h-chunk MMA: gates n-tiles + (ng0 warps) logits tile at cols 32-39
__device__ __forceinline__ void mma_hchunk(const float* A, const float* Bq, int c,
    float* d0, float* d1, float* dL, int am, int t4, int g0, int gid, bool ng0)
{
#pragma unroll
    for (int ks = 0; ks < 8; ++ks) {
        int ka = ks * 8 + t4;
        unsigned a0 = __float_as_uint(A[am + ka]);
        unsigned a1 = __float_as_uint(A[am + 8 * 68 + ka]);
        unsigned a2 = __float_as_uint(A[am + ka + 4]);
        unsigned a3 = __float_as_uint(A[am + 8 * 68 + ka + 4]);
        const float* B0 = Bq + (c * 64 + ks * 8 + t4) * 40;
        unsigned b0 = __float_as_uint(B0[g0 * 8 + gid]);
        unsigned b1 = __float_as_uint(B0[160 + g0 * 8 + gid]);
        mma8(d0, a0, a1, a2, a3, b0, b1);
        unsigned b2 = __float_as_uint(B0[(g0 + 1) * 8 + gid]);
        unsigned b3 = __float_as_uint(B0[160 + (g0 + 1) * 8 + gid]);
        mma8(d1, a0, a1, a2, a3, b2, b3);
        if (ng0) {
            unsigned b4 = __float_as_uint(B0[32 + gid]);
            unsigned b5 = __float_as_uint(B0[160 + 32 + gid]);
            mma8(dL, a0, a1, a2, a3, b4, b5);
        }
    }
}
// expl-chunk MMA: gates n-tiles only
__device__ __forceinline__ void mma_echunk(const float* A, const float* Bq, int c,
    float* d0, float* d1, int am, int t4, int g0, int gid)
{
#pragma unroll
    for (int ks = 0; ks < 8; ++ks) {
        int ka = ks * 8 + t4;
        unsigned a0 = __float_as_uint(A[am + ka]);
        unsigned a1 = __float_as_uint(A[am + 8 * 68 + ka]);
        unsigned a2 = __float_as_uint(A[am + ka + 4]);
        unsigned a3 = __float_as_uint(A[am + 8 * 68 + ka + 4]);
        const float* B0 = Bq + (c * 64 + ks * 8 + t4) * 40;
        unsigned b0 = __float_as_uint(B0[g0 * 8 + gid]);
        unsigned b1 = __float_as_uint(B0[160 + g0 * 8 + gid]);
        mma8(d0, a0, a1, a2, a3, b0, b1);
        unsigned b2 = __float_as_uint(B0[(g0 + 1) * 8 + gid]);
        unsigned b3 = __float_as_uint(B0[160 + (g0 + 1) * 8 + gid]);
        mma8(d1, a0, a1, a2, a3, b2, b3);
    }
}

// ---------------- persistent recurrence ----------------
__global__ void __launch_bounds__(256, 1) rnn_persist(
    const float* __restrict__ Whh_f, const float* __restrict__ Whh_b,
    const float* __restrict__ Mk_f,  const float* __restrict__ Mk_b,
    const int* __restrict__ lens,
    float* __restrict__ out)
{
    extern __shared__ float shm[];
    __shared__ float c_s[512];
    __shared__ float S_s[64];
    __shared__ float g_s[64 * 33];

    const int blk = blockIdx.x;
    const int d   = blk >> 6;
    const int j   = blk & 63;
    const float* Whh = d ? Whh_b : Whh_f;
    const float* Mk  = d ? Mk_b : Mk_f;

    const int tid  = threadIdx.x;
    const int w    = tid >> 5;
    const int lane = tid & 31;
    const int gid  = lane >> 2, t4 = lane & 3;
    const int mtile = w & 3, g0 = (w >> 2) * 2;
    const bool ng0 = (g0 == 0);
    const int row0 = mtile * 16 + gid, row1 = row0 + 8;
    const int am   = row0 * 68;
    const int cA   = g0 * 512 + j * 8 + 2 * t4;

    const int s0 = (j * MS) >> 6, s1 = ((j + 1) * MS) >> 6;
    const int scnt = s1 - s0;

    // one-time: pack resident B (Whh | Pt | Mk-slots) to tf32, pitch 40
    for (int idx = tid; idx < 832 * 40; idx += 256) {
        int k = idx / 40, n = idx - k * 40;
        float v;
        if (n < 32) {
            int ncol = (n >> 3) * 512 + j * 8 + (n & 7);
            v = (k < 512) ? Whh[(size_t)ncol * HH + k] : d_Pt[d][ncol][k - 512];
        } else {
            int sl = n - 32;
            v = (k < 512 && sl < scnt) ? Mk[(size_t)(s0 + sl) * HH + k] : 0.0f;
        }
        shm[k * 40 + n] = f2tf(v);
    }
    for (int i = tid; i < 512; i += 256) c_s[i] = 0.0f;
    __syncthreads();

    // Xp prefetch for t = 0
    float xg[8];
    {
        const float* xp = &d_Xp[d][0][0];
        float2 v;
        v = __ldcs((const float2*)(xp + (size_t)row0 * G4 + cA));       xg[0]=v.x; xg[1]=v.y;
        v = __ldcs((const float2*)(xp + (size_t)row1 * G4 + cA));       xg[2]=v.x; xg[3]=v.y;
        v = __ldcs((const float2*)(xp + (size_t)row0 * G4 + cA + 512)); xg[4]=v.x; xg[5]=v.y;
        v = __ldcs((const float2*)(xp + (size_t)row1 * G4 + cA + 512)); xg[6]=v.x; xg[7]=v.y;
    }

    for (int t = 0; t < TT; ++t) {
        const int rp = t & 1, wp = rp ^ 1;

        float aG0[4] = {xg[0], xg[1], xg[2], xg[3]};
        float aG1[4] = {xg[4], xg[5], xg[6], xg[7]};
        float aL[4]  = {0.0f, 0.0f, 0.0f, 0.0f};

        if (t > 0) {
            // ---- h part: gates-h + logits in one MMA sweep ----
            float vb[16];
            fetch_chunk(0, d, rp, tid, vb);
            store_chunk(0, tid, vb, shm + BQ_F);
            __syncthreads();
#pragma unroll 1
            for (int c = 0; c < 8; ++c) {
                if (c < 7) fetch_chunk(c + 1, d, rp, tid, vb);
                mma_hchunk(shm + BQ_F + (c & 1) * ACH, shm, c,
                           aG0, aG1, aL, am, t4, g0, gid, ng0);
                __syncthreads();
                if (c < 7) {
                    store_chunk(c + 1, tid, vb, shm + BQ_F + ((c + 1) & 1) * ACH);
                    __syncthreads();
                }
            }
            // ---- exp + expl store + per-block partial sums (ng0 warps) ----
            if (ng0) {
                float e0 = __expf(aL[0]), e1 = __expf(aL[1]);
                float e2 = __expf(aL[2]), e3 = __expf(aL[3]);
                int sl0 = 2 * t4, sl1 = sl0 + 1;
                if (sl0 >= scnt) { e0 = 0.0f; e2 = 0.0f; }
                if (sl1 >= scnt) { e1 = 0.0f; e3 = 0.0f; }
                if (sl0 < scnt) {
                    d_expl[d][s0 + sl0][row0] = e0;
                    d_expl[d][s0 + sl0][row1] = e2;
                }
                if (sl1 < scnt) {
                    d_expl[d][s0 + sl1][row0] = e1;
                    d_expl[d][s0 + sl1][row1] = e3;
                }
                float p0 = e0 + e1, p1 = e2 + e3;
                p0 += __shfl_xor_sync(0xffffffffu, p0, 1);
                p0 += __shfl_xor_sync(0xffffffffu, p0, 2);
                p1 += __shfl_xor_sync(0xffffffffu, p1, 1);
                p1 += __shfl_xor_sync(0xffffffffu, p1, 2);
                if (t4 == 0) {
                    d_part[d][j][row0] = p0;
                    d_part[d][j][row1] = p1;
                }
            }
            gridbar();

            // ---- expl part ----
            if (tid < 64) {
                float a = 0.0f;
#pragma unroll 16
                for (int jj = 0; jj < 64; ++jj) a += __ldcg(&d_part[d][jj][tid]);
                S_s[tid] = 1.0f / a;
            }
            float aE0[4] = {0,0,0,0}, aE1[4] = {0,0,0,0};
            float vb2[16];
            fetch_chunk(8, d, rp, tid, vb2);
            store_chunk(8, tid, vb2, shm + BQ_F);
            __syncthreads();
#pragma unroll 1
            for (int c = 8; c < 13; ++c) {
                if (c < 12) fetch_chunk(c + 1, d, rp, tid, vb2);
                mma_echunk(shm + BQ_F + (c & 1) * ACH, shm, c,
                           aE0, aE1, am, t4, g0, gid);
                __syncthreads();
                if (c < 12) {
                    store_chunk(c + 1, tid, vb2, shm + BQ_F + ((c + 1) & 1) * ACH);
                    __syncthreads();
                }
            }
            float si0 = S_s[row0], si1 = S_s[row1];
            aG0[0] += aE0[0] * si0; aG0[1] += aE0[1] * si0;
            aG0[2] += aE0[2] * si1; aG0[3] += aE0[3] * si1;
            aG1[0] += aE1[0] * si0; aG1[1] += aE1[1] * si0;
            aG1[2] += aE1[2] * si1; aG1[3] += aE1[3] * si1;
        }

        __syncthreads();
        {
            int cl0 = g0 * 8 + 2 * t4, cl1 = cl0 + 8;
            g_s[row0 * 33 + cl0] = aG0[0]; g_s[row0 * 33 + cl0 + 1] = aG0[1];
            g_s[row1 * 33 + cl0] = aG0[2]; g_s[row1 * 33 + cl0 + 1] = aG0[3];
            g_s[row0 * 33 + cl1] = aG1[0]; g_s[row0 * 33 + cl1 + 1] = aG1[1];
            g_s[row1 * 33 + cl1] = aG1[2]; g_s[row1 * 33 + cl1 + 1] = aG1[3];
        }
        __syncthreads();

#pragma unroll
        for (int pi = 0; pi < 2; ++pi) {
            int p = tid + pi * 256;
            int b = p >> 3, uu = p & 7;
            float gi = g_s[b * 33 + uu];
            float gf = g_s[b * 33 + 8 + uu];
            float gg = g_s[b * 33 + 16 + uu];
            float go = g_s[b * 33 + 24 + uu];
            float iv = 1.0f / (1.0f + __expf(-gi));
            float fv = 1.0f / (1.0f + __expf(-gf));
            float gv = tanhf(gg);
            float ov = 1.0f / (1.0f + __expf(-go));
            float c = fv * c_s[p] + iv * gv;
            c_s[p] = c;
            float h = ov * tanhf(c);
            d_hbuf[d][wp][b][j * 8 + uu] = h;
            int torig = d ? (TT - 1 - t) : t;
            float mval = (torig < lens[b]) ? h : 0.0f;
            out[((size_t)b * TT + torig) * 1024 + d * 512 + j * 8 + uu] = mval;
        }

        // Xp prefetch for t+1 (hidden behind the barrier wait)
        {
            int tn = (t + 1 < TT) ? (t + 1) : t;
            const float* xp = &d_Xp[d][(size_t)tn * BB][0];
            float2 v;
            v = __ldcs((const float2*)(xp + (size_t)row0 * G4 + cA));       xg[0]=v.x; xg[1]=v.y;
            v = __ldcs((const float2*)(xp + (size_t)row1 * G4 + cA));       xg[2]=v.x; xg[3]=v.y;
            v = __ldcs((const float2*)(xp + (size_t)row0 * G4 + cA + 512)); xg[4]=v.x; xg[5]=v.y;
            v = __ldcs((const float2*)(xp + (size_t)row1 * G4 + cA + 512)); xg[6]=v.x; xg[7]=v.y;
        }
        gridbar();
    }
}

// ---------------- launch ----------------
extern "C" void kernel_launch(void* const* d_in, const int* in_sizes, int n_in,
                              void* d_out, int out_size) {
    const float* seqs   = (const float*)d_in[0];
    const int*   ln     = (const int*)d_in[1];
    const float* Wih_f  = (const float*)d_in[2];
    const float* Whh_f  = (const float*)d_in[3];
    const float* bih_f  = (const float*)d_in[4];
    const float* bhh_f  = (const float*)d_in[5];
    const float* Mk_f   = (const float*)d_in[6];
    const float* Mv_f   = (const float*)d_in[7];
    const float* Wih_b  = (const float*)d_in[8];
    const float* Whh_b  = (const float*)d_in[9];
    const float* bih_b  = (const float*)d_in[10];
    const float* bhh_b  = (const float*)d_in[11];
    const float* Mk_b   = (const float*)d_in[12];
    const float* Mv_b   = (const float*)d_in[13];
    float* out = (float*)d_out;

    cudaFuncSetAttribute(rnn_persist,
                         cudaFuncAttributeMaxDynamicSharedMemorySize, DYN_BYTES);

    reset_kernel<<<1, 1>>>();
    xproj_kernel<<<dim3(16, 256, 2), 256>>>(seqs, Wih_f, Wih_b,
                                            bih_f, bhh_f, bih_b, bhh_b);
    p_kernel<<<dim3(5, 32, 2), 256>>>(Wih_f, Wih_b, Mv_f, Mv_b);
    rnn_persist<<<NBLK, 256, DYN_BYTES>>>(Whh_f, Whh_b, Mk_f, Mk_b, ln, out);
}

// round 9
// speedup vs baseline: 4.4138x; 1.1729x over previous
#include <cuda_runtime.h>

#define TT   512
#define BB   64
#define HH   512
#define G4   2048
#define MS   300
#define INW  812
#define NBLK 128
#define BQ_F 33280              /* 832 k x 40 n floats: resident weight smem */
#define ACH  4352               /* 64*68 floats per A chunk buffer           */
#define DYN_BYTES ((BQ_F + 2*ACH)*4)

/* xproj_mma smem: A[2][128*36] + B[2][32*72] floats */
#define XAP  36
#define XBP  72
#define XAS  (128*XAP)
#define XBS  (32*XBP)
#define XP_SMEM ((2*XAS + 2*XBS)*4)

// ---------------- device scratch ----------------
__device__ float d_Xp[2][TT * BB][G4];
__device__ float d_hbuf[2][2][BB][HH];
__device__ float d_expl[2][MS][BB];
__device__ float d_part[2][64][BB];
__device__ float d_Pt[2][G4][320];
__device__ unsigned d_barcnt;

__global__ void reset_kernel() { d_barcnt = 0u; }

__device__ __forceinline__ float f2tf(float f) {
    unsigned u; asm("cvt.rna.tf32.f32 %0, %1;" : "=r"(u) : "f"(f));
    return __uint_as_float(u);
}
__device__ __forceinline__ void mma8(float* d, unsigned a0, unsigned a1,
    unsigned a2, unsigned a3, unsigned b0, unsigned b1) {
    asm volatile("mma.sync.aligned.m16n8k8.row.col.f32.tf32.tf32.f32 "
        "{%0,%1,%2,%3},{%4,%5,%6,%7},{%8,%9},{%0,%1,%2,%3};"
        : "+f"(d[0]), "+f"(d[1]), "+f"(d[2]), "+f"(d[3])
        : "r"(a0), "r"(a1), "r"(a2), "r"(a3), "r"(b0), "r"(b1));
}

// ---------------- xproj via tf32 MMA: Xp = x @ Wx^T + b_ih + b_hh ----------
__global__ void __launch_bounds__(256, 1) xproj_mma(
    const float* __restrict__ seqs,
    const float* __restrict__ Wih_f, const float* __restrict__ Wih_b,
    const float* __restrict__ bih_f, const float* __restrict__ bhh_f,
    const float* __restrict__ bih_b, const float* __restrict__ bhh_b)
{
    extern __shared__ float xs[];
    float* As = xs;                 // [2][128*36]  (m-major, pitch 36)
    float* Bs = xs + 2 * XAS;       // [2][32*72]   (k-major, pitch 72)

    const int d  = blockIdx.z;
    const float* W  = d ? Wih_b : Wih_f;
    const float* bi = d ? bih_b : bih_f;
    const float* bh = d ? bhh_b : bhh_f;
    const int n0 = blockIdx.x * 64;
    const int m0 = blockIdx.y * 128;

    const int tid  = threadIdx.x;
    const int w    = tid >> 5, lane = tid & 31;
    const int gid  = lane >> 2, t4 = lane & 3;
    const int wm   = w & 3, wn = w >> 2;

    // A loader mapping: 2 threads per row, 16 k-floats each
    const int ar = tid >> 1;
    const int ak = (tid & 1) * 16;
    const int grow = m0 + ar;
    const int att  = grow >> 6;
    const int abb  = grow & 63;
    const int tsrc = d ? (TT - 1 - att) : att;
    const float* aptr = seqs + ((size_t)abb * TT + tsrc) * HH + ak;

    // B loader mapping: 4 threads per W-row (n), 2 float4 each (k, k+16)
    const int bn = tid >> 2;
    const int bk = (tid & 3) * 4;
    const float* bptr = W + (size_t)(n0 + bn) * INW + bk;

    float acc[2][4][4];
#pragma unroll
    for (int mt = 0; mt < 2; ++mt)
#pragma unroll
        for (int nt = 0; nt < 4; ++nt)
#pragma unroll
            for (int i = 0; i < 4; ++i) acc[mt][nt][i] = 0.0f;

    float4 av[4], bv[2];
    // prefetch stage 0
#pragma unroll
    for (int q = 0; q < 4; ++q) av[q] = *(const float4*)(aptr + q * 4);
    bv[0] = *(const float4*)(bptr);
    bv[1] = *(const float4*)(bptr + 16);
    {
        float* A0 = As; float* B0 = Bs;
#pragma unroll
        for (int q = 0; q < 4; ++q) {
            float4 sv;
            sv.x = f2tf(av[q].x); sv.y = f2tf(av[q].y);
            sv.z = f2tf(av[q].z); sv.w = f2tf(av[q].w);
            *(float4*)(A0 + ar * XAP + ak + q * 4) = sv;
        }
        B0[(bk + 0) * XBP + bn] = f2tf(bv[0].x);
        B0[(bk + 1) * XBP + bn] = f2tf(bv[0].y);
        B0[(bk + 2) * XBP + bn] = f2tf(bv[0].z);
        B0[(bk + 3) * XBP + bn] = f2tf(bv[0].w);
        B0[(16 + bk + 0) * XBP + bn] = f2tf(bv[1].x);
        B0[(16 + bk + 1) * XBP + bn] = f2tf(bv[1].y);
        B0[(16 + bk + 2) * XBP + bn] = f2tf(bv[1].z);
        B0[(16 + bk + 3) * XBP + bn] = f2tf(bv[1].w);
    }
    __syncthreads();

#pragma unroll 1
    for (int kt = 0; kt < 16; ++kt) {
        if (kt < 15) {
            int k0 = (kt + 1) * 32;
#pragma unroll
            for (int q = 0; q < 4; ++q) av[q] = *(const float4*)(aptr + k0 + q * 4);
            bv[0] = *(const float4*)(bptr + k0);
            bv[1] = *(const float4*)(bptr + k0 + 16);
        }
        const float* A = As + (kt & 1) * XAS;
        const float* B = Bs + (kt & 1) * XBS;
#pragma unroll
        for (int ks = 0; ks < 4; ++ks) {
            int ka = ks * 8 + t4;
#pragma unroll
            for (int mt = 0; mt < 2; ++mt) {
                int base = (wm * 32 + mt * 16 + gid) * XAP + ka;
                unsigned a0 = __float_as_uint(A[base]);
                unsigned a1 = __float_as_uint(A[base + 8 * XAP]);
                unsigned a2 = __float_as_uint(A[base + 4]);
                unsigned a3 = __float_as_uint(A[base + 8 * XAP + 4]);
#pragma unroll
                for (int nt = 0; nt < 4; ++nt) {
                    unsigned b0 = __float_as_uint(B[ka * XBP + wn * 32 + nt * 8 + gid]);
                    unsigned b1 = __float_as_uint(B[(ka + 4) * XBP + wn * 32 + nt * 8 + gid]);
                    mma8(acc[mt][nt], a0, a1, a2, a3, b0, b1);
                }
            }
        }
        __syncthreads();
        if (kt < 15) {
            float* A1 = As + ((kt + 1) & 1) * XAS;
            float* B1 = Bs + ((kt + 1) & 1) * XBS;
#pragma unroll
            for (int q = 0; q < 4; ++q) {
                float4 sv;
                sv.x = f2tf(av[q].x); sv.y = f2tf(av[q].y);
                sv.z = f2tf(av[q].z); sv.w = f2tf(av[q].w);
                *(float4*)(A1 + ar * XAP + ak + q * 4) = sv;
            }
            B1[(bk + 0) * XBP + bn] = f2tf(bv[0].x);
            B1[(bk + 1) * XBP + bn] = f2tf(bv[0].y);
            B1[(bk + 2) * XBP + bn] = f2tf(bv[0].z);
            B1[(bk + 3) * XBP + bn] = f2tf(bv[0].w);
            B1[(16 + bk + 0) * XBP + bn] = f2tf(bv[1].x);
            B1[(16 + bk + 1) * XBP + bn] = f2tf(bv[1].y);
            B1[(16 + bk + 2) * XBP + bn] = f2tf(bv[1].z);
            B1[(16 + bk + 3) * XBP + bn] = f2tf(bv[1].w);
            __syncthreads();
        }
    }

    // epilogue: bias + store
#pragma unroll
    for (int nt = 0; nt < 4; ++nt) {
        int col = n0 + wn * 32 + nt * 8 + 2 * t4;
        float b0 = bi[col] + bh[col];
        float b1 = bi[col + 1] + bh[col + 1];
#pragma unroll
        for (int mt = 0; mt < 2; ++mt) {
            int r0 = m0 + wm * 32 + mt * 16 + gid;
            float2 v0 = {acc[mt][nt][0] + b0, acc[mt][nt][1] + b1};
            float2 v1 = {acc[mt][nt][2] + b0, acc[mt][nt][3] + b1};
            *(float2*)&d_Xp[d][r0][col]     = v0;
            *(float2*)&d_Xp[d][r0 + 8][col] = v1;
        }
    }
}

// ---------------- Pt precompute (unchanged control) ----------------
__global__ void __launch_bounds__(256, 2) p_kernel(
    const float* __restrict__ Wih_f, const float* __restrict__ Wih_b,
    const float* __restrict__ Mv_f,  const float* __restrict__ Mv_b)
{
    const int d = blockIdx.z;
    const float* W  = d ? Wih_b : Wih_f;
    const float* Mv = d ? Mv_b : Mv_f;
    const int n0 = blockIdx.x * 64;
    const int m0 = blockIdx.y * 64;

    __shared__ float As[8][68], Bs[8][68];
    const int tid = threadIdx.x;
    const int ty = tid >> 4, tx = tid & 15;

    float acc[4][4];
#pragma unroll
    for (int r = 0; r < 4; ++r)
#pragma unroll
        for (int c = 0; c < 4; ++c) acc[r][c] = 0.0f;

    for (int k0 = 0; k0 < 304; k0 += 8) {
        __syncthreads();
#pragma unroll
        for (int i = 0; i < 2; ++i) {
            int idx = i * 256 + tid;
            int r = idx & 63, kk = idx >> 6;
            int k = k0 + kk;
            As[kk][r] = (k < MS) ? W[(size_t)(m0 + r) * INW + 512 + k] : 0.0f;
            Bs[kk][r] = (k < MS && n0 + r < MS) ? Mv[(size_t)k * MS + n0 + r] : 0.0f;
        }
        __syncthreads();
#pragma unroll
        for (int kk = 0; kk < 8; ++kk) {
            float a[4], b[4];
#pragma unroll
            for (int r = 0; r < 4; ++r) a[r] = As[kk][ty * 4 + r];
#pragma unroll
            for (int c = 0; c < 4; ++c) b[c] = Bs[kk][tx * 4 + c];
#pragma unroll
            for (int r = 0; r < 4; ++r)
#pragma unroll
                for (int c = 0; c < 4; ++c) acc[r][c] += a[r] * b[c];
        }
    }
#pragma unroll
    for (int r = 0; r < 4; ++r)
#pragma unroll
        for (int c = 0; c < 4; ++c)
            d_Pt[d][m0 + ty * 4 + r][n0 + tx * 4 + c] = acc[r][c];
}

// ---------------- grid barrier (tight spin, late backoff) ----------------
__device__ __forceinline__ void gridbar() {
    __threadfence();
    __syncthreads();
    if (threadIdx.x == 0) {
        unsigned t = atomicAdd(&d_barcnt, 1u);
        unsigned target = (t / NBLK + 1u) * NBLK;
        int spins = 0;
        while (*(volatile unsigned*)&d_barcnt < target) {
            if (++spins > 256) __nanosleep(32);
        }
    }
    __syncthreads();
    __threadfence();
}

// ---------------- A-chunk staging ----------------
__device__ __forceinline__ void fetch_chunk(int c, int d, int rp, int tid, float* vb) {
    if (c < 8) {
        const float* hb = &d_hbuf[d][rp][0][0];
#pragma unroll
        for (int jj = 0; jj < 4; ++jj) {
            int idx = jj * 256 + tid;
            int b = idx >> 4, kq = idx & 15;
            float4 v = __ldcg((const float4*)(hb + b * HH + c * 64 + kq * 4));
            vb[jj*4+0] = v.x; vb[jj*4+1] = v.y; vb[jj*4+2] = v.z; vb[jj*4+3] = v.w;
        }
    } else {
#pragma unroll
        for (int jj = 0; jj < 16; ++jj) {
            int idx = jj * 256 + tid;
            int sl = idx >> 6, b = idx & 63;
            int s = (c - 8) * 64 + sl;
            vb[jj] = (s < MS) ? __ldcg(&d_expl[d][s][b]) : 0.0f;
        }
    }
}
__device__ __forceinline__ void store_chunk(int c, int tid, const float* vb, float* A) {
    if (c < 8) {
#pragma unroll
        for (int jj = 0; jj < 4; ++jj) {
            int idx = jj * 256 + tid;
            int b = idx >> 4, kq = idx & 15;
            float4 sv;
            sv.x = f2tf(vb[jj*4+0]); sv.y = f2tf(vb[jj*4+1]);
            sv.z = f2tf(vb[jj*4+2]); sv.w = f2tf(vb[jj*4+3]);
            *(float4*)(A + b * 68 + kq * 4) = sv;
        }
    } else {
#pragma unroll
        for (int jj = 0; jj < 16; ++jj) {
            int idx = jj * 256 + tid;
            int sl = idx >> 6, b = idx & 63;
            A[b * 68 + sl] = f2tf(vb[jj]);
        }
    }
}

__device__ __forceinline__ void mma_hchunk(const float* A, const float* Bq, int c,
    float* d0, float* d1, float* dL, int am, int t4, int g0, int gid, bool ng0)
{
#pragma unroll
    for (int ks = 0; ks < 8; ++ks) {
        int ka = ks * 8 + t4;
        unsigned a0 = __float_as_uint(A[am + ka]);
        unsigned a1 = __float_as_uint(A[am + 8 * 68 + ka]);
        unsigned a2 = __float_as_uint(A[am + ka + 4]);
        unsigned a3 = __float_as_uint(A[am + 8 * 68 + ka + 4]);
        const float* B0 = Bq + (c * 64 + ks * 8 + t4) * 40;
        unsigned b0 = __float_as_uint(B0[g0 * 8 + gid]);
        unsigned b1 = __float_as_uint(B0[160 + g0 * 8 + gid]);
        mma8(d0, a0, a1, a2, a3, b0, b1);
        unsigned b2 = __float_as_uint(B0[(g0 + 1) * 8 + gid]);
        unsigned b3 = __float_as_uint(B0[160 + (g0 + 1) * 8 + gid]);
        mma8(d1, a0, a1, a2, a3, b2, b3);
        if (ng0) {
            unsigned b4 = __float_as_uint(B0[32 + gid]);
            unsigned b5 = __float_as_uint(B0[160 + 32 + gid]);
            mma8(dL, a0, a1, a2, a3, b4, b5);
        }
    }
}
__device__ __forceinline__ void mma_echunk(const float* A, const float* Bq, int c,
    float* d0, float* d1, int am, int t4, int g0, int gid)
{
#pragma unroll
    for (int ks = 0; ks < 8; ++ks) {
        int ka = ks * 8 + t4;
        unsigned a0 = __float_as_uint(A[am + ka]);
        unsigned a1 = __float_as_uint(A[am + 8 * 68 + ka]);
        unsigned a2 = __float_as_uint(A[am + ka + 4]);
        unsigned a3 = __float_as_uint(A[am + 8 * 68 + ka + 4]);
        const float* B0 = Bq + (c * 64 + ks * 8 + t4) * 40;
        unsigned b0 = __float_as_uint(B0[g0 * 8 + gid]);
        unsigned b1 = __float_as_uint(B0[160 + g0 * 8 + gid]);
        mma8(d0, a0, a1, a2, a3, b0, b1);
        unsigned b2 = __float_as_uint(B0[(g0 + 1) * 8 + gid]);
        unsigned b3 = __float_as_uint(B0[160 + (g0 + 1) * 8 + gid]);
        mma8(d1, a0, a1, a2, a3, b2, b3);
    }
}

// ---------------- persistent recurrence (unchanged from R7) ----------------
__global__ void __launch_bounds__(256, 1) rnn_persist(
    const float* __restrict__ Whh_f, const float* __restrict__ Whh_b,
    const float* __restrict__ Mk_f,  const float* __restrict__ Mk_b,
    const int* __restrict__ lens,
    float* __restrict__ out)
{
    extern __shared__ float shm[];
    __shared__ float c_s[512];
    __shared__ float S_s[64];
    __shared__ float g_s[64 * 33];

    const int blk = blockIdx.x;
    const int d   = blk >> 6;
    const int j   = blk & 63;
    const float* Whh = d ? Whh_b : Whh_f;
    const float* Mk  = d ? Mk_b : Mk_f;

    const int tid  = threadIdx.x;
    const int w    = tid >> 5;
    const int lane = tid & 31;
    const int gid  = lane >> 2, t4 = lane & 3;
    const int mtile = w & 3, g0 = (w >> 2) * 2;
    const bool ng0 = (g0 == 0);
    const int row0 = mtile * 16 + gid, row1 = row0 + 8;
    const int am   = row0 * 68;
    const int cA   = g0 * 512 + j * 8 + 2 * t4;

    const int s0 = (j * MS) >> 6, s1 = ((j + 1) * MS) >> 6;
    const int scnt = s1 - s0;

    for (int idx = tid; idx < 832 * 40; idx += 256) {
        int k = idx / 40, n = idx - k * 40;
        float v;
        if (n < 32) {
            int ncol = (n >> 3) * 512 + j * 8 + (n & 7);
            v = (k < 512) ? Whh[(size_t)ncol * HH + k] : d_Pt[d][ncol][k - 512];
        } else {
            int sl = n - 32;
            v = (k < 512 && sl < scnt) ? Mk[(size_t)(s0 + sl) * HH + k] : 0.0f;
        }
        shm[k * 40 + n] = f2tf(v);
    }
    for (int i = tid; i < 512; i += 256) c_s[i] = 0.0f;
    __syncthreads();

    float xg[8];
    {
        const float* xp = &d_Xp[d][0][0];
        float2 v;
        v = __ldcs((const float2*)(xp + (size_t)row0 * G4 + cA));       xg[0]=v.x; xg[1]=v.y;
        v = __ldcs((const float2*)(xp + (size_t)row1 * G4 + cA));       xg[2]=v.x; xg[3]=v.y;
        v = __ldcs((const float2*)(xp + (size_t)row0 * G4 + cA + 512)); xg[4]=v.x; xg[5]=v.y;
        v = __ldcs((const float2*)(xp + (size_t)row1 * G4 + cA + 512)); xg[6]=v.x; xg[7]=v.y;
    }

    for (int t = 0; t < TT; ++t) {
        const int rp = t & 1, wp = rp ^ 1;

        float aG0[4] = {xg[0], xg[1], xg[2], xg[3]};
        float aG1[4] = {xg[4], xg[5], xg[6], xg[7]};
        float aL[4]  = {0.0f, 0.0f, 0.0f, 0.0f};

        if (t > 0) {
            float vb[16];
            fetch_chunk(0, d, rp, tid, vb);
            store_chunk(0, tid, vb, shm + BQ_F);
            __syncthreads();
#pragma unroll 1
            for (int c = 0; c < 8; ++c) {
                if (c < 7) fetch_chunk(c + 1, d, rp, tid, vb);
                mma_hchunk(shm + BQ_F + (c & 1) * ACH, shm, c,
                           aG0, aG1, aL, am, t4, g0, gid, ng0);
                __syncthreads();
                if (c < 7) {
                    store_chunk(c + 1, tid, vb, shm + BQ_F + ((c + 1) & 1) * ACH);
                    __syncthreads();
                }
            }
            if (ng0) {
                float e0 = __expf(aL[0]), e1 = __expf(aL[1]);
                float e2 = __expf(aL[2]), e3 = __expf(aL[3]);
                int sl0 = 2 * t4, sl1 = sl0 + 1;
                if (sl0 >= scnt) { e0 = 0.0f; e2 = 0.0f; }
                if (sl1 >= scnt) { e1 = 0.0f; e3 = 0.0f; }
                if (sl0 < scnt) {
                    d_expl[d][s0 + sl0][row0] = e0;
                    d_expl[d][s0 + sl0][row1] = e2;
                }
                if (sl1 < scnt) {
                    d_expl[d][s0 + sl1][row0] = e1;
                    d_expl[d][s0 + sl1][row1] = e3;
                }
                float p0 = e0 + e1, p1 = e2 + e3;
                p0 += __shfl_xor_sync(0xffffffffu, p0, 1);
                p0 += __shfl_xor_sync(0xffffffffu, p0, 2);
                p1 += __shfl_xor_sync(0xffffffffu, p1, 1);
                p1 += __shfl_xor_sync(0xffffffffu, p1, 2);
                if (t4 == 0) {
                    d_part[d][j][row0] = p0;
                    d_part[d][j][row1] = p1;
                }
            }
            gridbar();

            if (tid < 64) {
                float a = 0.0f;
#pragma unroll 16
                for (int jj = 0; jj < 64; ++jj) a += __ldcg(&d_part[d][jj][tid]);
                S_s[tid] = 1.0f / a;
            }
            float aE0[4] = {0,0,0,0}, aE1[4] = {0,0,0,0};
            float vb2[16];
            fetch_chunk(8, d, rp, tid, vb2);
            store_chunk(8, tid, vb2, shm + BQ_F);
            __syncthreads();
#pragma unroll 1
            for (int c = 8; c < 13; ++c) {
                if (c < 12) fetch_chunk(c + 1, d, rp, tid, vb2);
                mma_echunk(shm + BQ_F + (c & 1) * ACH, shm, c,
                           aE0, aE1, am, t4, g0, gid);
                __syncthreads();
                if (c < 12) {
                    store_chunk(c + 1, tid, vb2, shm + BQ_F + ((c + 1) & 1) * ACH);
                    __syncthreads();
                }
            }
            float si0 = S_s[row0], si1 = S_s[row1];
            aG0[0] += aE0[0] * si0; aG0[1] += aE0[1] * si0;
            aG0[2] += aE0[2] * si1; aG0[3] += aE0[3] * si1;
            aG1[0] += aE1[0] * si0; aG1[1] += aE1[1] * si0;
            aG1[2] += aE1[2] * si1; aG1[3] += aE1[3] * si1;
        }

        __syncthreads();
        {
            int cl0 = g0 * 8 + 2 * t4, cl1 = cl0 + 8;
            g_s[row0 * 33 + cl0] = aG0[0]; g_s[row0 * 33 + cl0 + 1] = aG0[1];
            g_s[row1 * 33 + cl0] = aG0[2]; g_s[row1 * 33 + cl0 + 1] = aG0[3];
            g_s[row0 * 33 + cl1] = aG1[0]; g_s[row0 * 33 + cl1 + 1] = aG1[1];
            g_s[row1 * 33 + cl1] = aG1[2]; g_s[row1 * 33 + cl1 + 1] = aG1[3];
        }
        __syncthreads();

#pragma unroll
        for (int pi = 0; pi < 2; ++pi) {
            int p = tid + pi * 256;
            int b = p >> 3, uu = p & 7;
            float gi = g_s[b * 33 + uu];
            float gf = g_s[b * 33 + 8 + uu];
            float gg = g_s[b * 33 + 16 + uu];
            float go = g_s[b * 33 + 24 + uu];
            float iv = 1.0f / (1.0f + __expf(-gi));
            float fv = 1.0f / (1.0f + __expf(-gf));
            float gv = tanhf(gg);
            float ov = 1.0f / (1.0f + __expf(-go));
            float c = fv * c_s[p] + iv * gv;
            c_s[p] = c;
            float h = ov * tanhf(c);
            d_hbuf[d][wp][b][j * 8 + uu] = h;
            int torig = d ? (TT - 1 - t) : t;
            float mval = (torig < lens[b]) ? h : 0.0f;
            out[((size_t)b * TT + torig) * 1024 + d * 512 + j * 8 + uu] = mval;
        }

        {
            int tn = (t + 1 < TT) ? (t + 1) : t;
            const float* xp = &d_Xp[d][(size_t)tn * BB][0];
            float2 v;
            v = __ldcs((const float2*)(xp + (size_t)row0 * G4 + cA));       xg[0]=v.x; xg[1]=v.y;
            v = __ldcs((const float2*)(xp + (size_t)row1 * G4 + cA));       xg[2]=v.x; xg[3]=v.y;
            v = __ldcs((const float2*)(xp + (size_t)row0 * G4 + cA + 512)); xg[4]=v.x; xg[5]=v.y;
            v = __ldcs((const float2*)(xp + (size_t)row1 * G4 + cA + 512)); xg[6]=v.x; xg[7]=v.y;
        }
        gridbar();
    }
}

// ---------------- launch ----------------
extern "C" void kernel_launch(void* const* d_in, const int* in_sizes, int n_in,
                              void* d_out, int out_size) {
    const float* seqs   = (const float*)d_in[0];
    const int*   ln     = (const int*)d_in[1];
    const float* Wih_f  = (const float*)d_in[2];
    const float* Whh_f  = (const float*)d_in[3];
    const float* bih_f  = (const float*)d_in[4];
    const float* bhh_f  = (const float*)d_in[5];
    const float* Mk_f   = (const float*)d_in[6];
    const float* Mv_f   = (const float*)d_in[7];
    const float* Wih_b  = (const float*)d_in[8];
    const float* Whh_b  = (const float*)d_in[9];
    const float* bih_b  = (const float*)d_in[10];
    const float* bhh_b  = (const float*)d_in[11];
    const float* Mk_b   = (const float*)d_in[12];
    const float* Mv_b   = (const float*)d_in[13];
    float* out = (float*)d_out;

    cudaFuncSetAttribute(rnn_persist,
                         cudaFuncAttributeMaxDynamicSharedMemorySize, DYN_BYTES);
    cudaFuncSetAttribute(xproj_mma,
                         cudaFuncAttributeMaxDynamicSharedMemorySize, XP_SMEM);

    reset_kernel<<<1, 1>>>();
    xproj_mma<<<dim3(32, 256, 2), 256, XP_SMEM>>>(seqs, Wih_f, Wih_b,
                                                  bih_f, bhh_f, bih_b, bhh_b);
    p_kernel<<<dim3(5, 32, 2), 256>>>(Wih_f, Wih_b, Mv_f, Mv_b);
    rnn_persist<<<NBLK, 256, DYN_BYTES>>>(Whh_f, Whh_b, Mk_f, Mk_b, ln, out);
}

// round 10
// speedup vs baseline: 4.7950x; 1.0864x over previous
#include <cuda_runtime.h>

#define TT   512
#define BB   64
#define HH   512
#define G4   2048
#define MS   300
#define INW  812
#define NBLK 128
#define BQ_F 33280              /* 832 k x 40 n resident weight smem (floats) */
#define PIT  132                /* A-chunk row pitch (floats)                 */
#define ABUF (64*PIT)           /* 8448 floats per A chunk buffer             */
#define DYN_BYTES ((BQ_F + 2*ABUF)*4)

#define XAP  36
#define XBP  72
#define XAS  (128*XAP)
#define XBS  (32*XBP)
#define XP_SMEM ((2*XAS + 2*XBS)*4)

// ---------------- device scratch ----------------
__device__ float d_Xp[2][TT * BB][G4];
__device__ float d_hbuf[2][2][BB][HH];      // h, stored tf32-rounded
__device__ float d_expl[2][BB][320];        // exp(logits), batch-major, tf32-rounded, zero-padded
__device__ float d_part[2][64][BB];
__device__ float d_Pt[2][G4][320];
__device__ unsigned d_flag[NBLK * 32];      // per-block epoch flags, 128B apart

__global__ void reset_kernel() {
    int i = blockIdx.x * blockDim.x + threadIdx.x;
    int n = gridDim.x * blockDim.x;
    for (int x = i; x < NBLK * 32; x += n) d_flag[x] = 0u;
    float* e = &d_expl[0][0][0];
    for (int x = i; x < 2 * BB * 320; x += n) e[x] = 0.0f;
}

__device__ __forceinline__ float f2tf(float f) {
    unsigned u; asm("cvt.rna.tf32.f32 %0, %1;" : "=r"(u) : "f"(f));
    return __uint_as_float(u);
}
__device__ __forceinline__ void mma8(float* d, unsigned a0, unsigned a1,
    unsigned a2, unsigned a3, unsigned b0, unsigned b1) {
    asm volatile("mma.sync.aligned.m16n8k8.row.col.f32.tf32.tf32.f32 "
        "{%0,%1,%2,%3},{%4,%5,%6,%7},{%8,%9},{%0,%1,%2,%3};"
        : "+f"(d[0]), "+f"(d[1]), "+f"(d[2]), "+f"(d[3])
        : "r"(a0), "r"(a1), "r"(a2), "r"(a3), "r"(b0), "r"(b1));
}
__device__ __forceinline__ void cpa16(unsigned dst, const void* src) {
    asm volatile("cp.async.cg.shared.global [%0], [%1], 16;" :: "r"(dst), "l"(src));
}
#define CPA_COMMIT() asm volatile("cp.async.commit_group;")
template <int N> __device__ __forceinline__ void cpa_wait() {
    asm volatile("cp.async.wait_group %0;" :: "n"(N));
}
__device__ __forceinline__ unsigned ld_acq(const unsigned* p) {
    unsigned v;
    asm volatile("ld.acquire.gpu.global.u32 %0, [%1];" : "=r"(v) : "l"(p));
    return v;
}

// ---------------- xproj via tf32 MMA (unchanged from R8) ----------------
__global__ void __launch_bounds__(256, 1) xproj_mma(
    const float* __restrict__ seqs,
    const float* __restrict__ Wih_f, const float* __restrict__ Wih_b,
    const float* __restrict__ bih_f, const float* __restrict__ bhh_f,
    const float* __restrict__ bih_b, const float* __restrict__ bhh_b)
{
    extern __shared__ float xs[];
    float* As = xs;
    float* Bs = xs + 2 * XAS;

    const int d  = blockIdx.z;
    const float* W  = d ? Wih_b : Wih_f;
    const float* bi = d ? bih_b : bih_f;
    const float* bh = d ? bhh_b : bhh_f;
    const int n0 = blockIdx.x * 64;
    const int m0 = blockIdx.y * 128;

    const int tid  = threadIdx.x;
    const int w    = tid >> 5, lane = tid & 31;
    const int gid  = lane >> 2, t4 = lane & 3;
    const int wm   = w & 3, wn = w >> 2;

    const int ar = tid >> 1;
    const int ak = (tid & 1) * 16;
    const int grow = m0 + ar;
    const int att  = grow >> 6;
    const int abb  = grow & 63;
    const int tsrc = d ? (TT - 1 - att) : att;
    const float* aptr = seqs + ((size_t)abb * TT + tsrc) * HH + ak;

    const int bn = tid >> 2;
    const int bk = (tid & 3) * 4;
    const float* bptr = W + (size_t)(n0 + bn) * INW + bk;

    float acc[2][4][4];
#pragma unroll
    for (int mt = 0; mt < 2; ++mt)
#pragma unroll
        for (int nt = 0; nt < 4; ++nt)
#pragma unroll
            for (int i = 0; i < 4; ++i) acc[mt][nt][i] = 0.0f;

    float4 av[4], bv[2];
#pragma unroll
    for (int q = 0; q < 4; ++q) av[q] = *(const float4*)(aptr + q * 4);
    bv[0] = *(const float4*)(bptr);
    bv[1] = *(const float4*)(bptr + 16);
    {
        float* A0 = As; float* B0 = Bs;
#pragma unroll
        for (int q = 0; q < 4; ++q) {
            float4 sv;
            sv.x = f2tf(av[q].x); sv.y = f2tf(av[q].y);
            sv.z = f2tf(av[q].z); sv.w = f2tf(av[q].w);
            *(float4*)(A0 + ar * XAP + ak + q * 4) = sv;
        }
        B0[(bk + 0) * XBP + bn] = f2tf(bv[0].x);
        B0[(bk + 1) * XBP + bn] = f2tf(bv[0].y);
        B0[(bk + 2) * XBP + bn] = f2tf(bv[0].z);
        B0[(bk + 3) * XBP + bn] = f2tf(bv[0].w);
        B0[(16 + bk + 0) * XBP + bn] = f2tf(bv[1].x);
        B0[(16 + bk + 1) * XBP + bn] = f2tf(bv[1].y);
        B0[(16 + bk + 2) * XBP + bn] = f2tf(bv[1].z);
        B0[(16 + bk + 3) * XBP + bn] = f2tf(bv[1].w);
    }
    __syncthreads();

#pragma unroll 1
    for (int kt = 0; kt < 16; ++kt) {
        if (kt < 15) {
            int k0 = (kt + 1) * 32;
#pragma unroll
            for (int q = 0; q < 4; ++q) av[q] = *(const float4*)(aptr + k0 + q * 4);
            bv[0] = *(const float4*)(bptr + k0);
            bv[1] = *(const float4*)(bptr + k0 + 16);
        }
        const float* A = As + (kt & 1) * XAS;
        const float* B = Bs + (kt & 1) * XBS;
#pragma unroll
        for (int ks = 0; ks < 4; ++ks) {
            int ka = ks * 8 + t4;
#pragma unroll
            for (int mt = 0; mt < 2; ++mt) {
                int base = (wm * 32 + mt * 16 + gid) * XAP + ka;
                unsigned a0 = __float_as_uint(A[base]);
                unsigned a1 = __float_as_uint(A[base + 8 * XAP]);
                unsigned a2 = __float_as_uint(A[base + 4]);
                unsigned a3 = __float_as_uint(A[base + 8 * XAP + 4]);
#pragma unroll
                for (int nt = 0; nt < 4; ++nt) {
                    unsigned b0 = __float_as_uint(B[ka * XBP + wn * 32 + nt * 8 + gid]);
                    unsigned b1 = __float_as_uint(B[(ka + 4) * XBP + wn * 32 + nt * 8 + gid]);
                    mma8(acc[mt][nt], a0, a1, a2, a3, b0, b1);
                }
            }
        }
        __syncthreads();
        if (kt < 15) {
            float* A1 = As + ((kt + 1) & 1) * XAS;
            float* B1 = Bs + ((kt + 1) & 1) * XBS;
#pragma unroll
            for (int q = 0; q < 4; ++q) {
                float4 sv;
                sv.x = f2tf(av[q].x); sv.y = f2tf(av[q].y);
                sv.z = f2tf(av[q].z); sv.w = f2tf(av[q].w);
                *(float4*)(A1 + ar * XAP + ak + q * 4) = sv;
            }
            B1[(bk + 0) * XBP + bn] = f2tf(bv[0].x);
            B1[(bk + 1) * XBP + bn] = f2tf(bv[0].y);
            B1[(bk + 2) * XBP + bn] = f2tf(bv[0].z);
            B1[(bk + 3) * XBP + bn] = f2tf(bv[0].w);
            B1[(16 + bk + 0) * XBP + bn] = f2tf(bv[1].x);
            B1[(16 + bk + 1) * XBP + bn] = f2tf(bv[1].y);
            B1[(16 + bk + 2) * XBP + bn] = f2tf(bv[1].z);
            B1[(16 + bk + 3) * XBP + bn] = f2tf(bv[1].w);
            __syncthreads();
        }
    }

#pragma unroll
    for (int nt = 0; nt < 4; ++nt) {
        int col = n0 + wn * 32 + nt * 8 + 2 * t4;
        float b0 = bi[col] + bh[col];
        float b1 = bi[col + 1] + bh[col + 1];
#pragma unroll
        for (int mt = 0; mt < 2; ++mt) {
            int r0 = m0 + wm * 32 + mt * 16 + gid;
            float2 v0 = {acc[mt][nt][0] + b0, acc[mt][nt][1] + b1};
            float2 v1 = {acc[mt][nt][2] + b0, acc[mt][nt][3] + b1};
            *(float2*)&d_Xp[d][r0][col]     = v0;
            *(float2*)&d_Xp[d][r0 + 8][col] = v1;
        }
    }
}

// ---------------- Pt precompute (unchanged) ----------------
__global__ void __launch_bounds__(256, 2) p_kernel(
    const float* __restrict__ Wih_f, const float* __restrict__ Wih_b,
    const float* __restrict__ Mv_f,  const float* __restrict__ Mv_b)
{
    const int d = blockIdx.z;
    const float* W  = d ? Wih_b : Wih_f;
    const float* Mv = d ? Mv_b : Mv_f;
    const int n0 = blockIdx.x * 64;
    const int m0 = blockIdx.y * 64;

    __shared__ float As[8][68], Bs[8][68];
    const int tid = threadIdx.x;
    const int ty = tid >> 4, tx = tid & 15;

    float acc[4][4];
#pragma unroll
    for (int r = 0; r < 4; ++r)
#pragma unroll
        for (int c = 0; c < 4; ++c) acc[r][c] = 0.0f;

    for (int k0 = 0; k0 < 304; k0 += 8) {
        __syncthreads();
#pragma unroll
        for (int i = 0; i < 2; ++i) {
            int idx = i * 256 + tid;
            int r = idx & 63, kk = idx >> 6;
            int k = k0 + kk;
            As[kk][r] = (k < MS) ? W[(size_t)(m0 + r) * INW + 512 + k] : 0.0f;
            Bs[kk][r] = (k < MS && n0 + r < MS) ? Mv[(size_t)k * MS + n0 + r] : 0.0f;
        }
        __syncthreads();
#pragma unroll
        for (int kk = 0; kk < 8; ++kk) {
            float a[4], b[4];
#pragma unroll
            for (int r = 0; r < 4; ++r) a[r] = As[kk][ty * 4 + r];
#pragma unroll
            for (int c = 0; c < 4; ++c) b[c] = Bs[kk][tx * 4 + c];
#pragma unroll
            for (int r = 0; r < 4; ++r)
#pragma unroll
                for (int c = 0; c < 4; ++c) acc[r][c] += a[r] * b[c];
        }
    }
#pragma unroll
    for (int r = 0; r < 4; ++r)
#pragma unroll
        for (int c = 0; c < 4; ++c)
            d_Pt[d][m0 + ty * 4 + r][n0 + tx * 4 + c] = acc[r][c];
}

// ---------------- distributed-flag grid barrier ----------------
__device__ __forceinline__ void flagbar(unsigned ep) {
    __syncthreads();
    if (threadIdx.x == 0) {
        __threadfence();
        atomicExch(&d_flag[blockIdx.x << 5], ep);
    }
    if (threadIdx.x < NBLK) {
        int spins = 0;
        while (ld_acq(&d_flag[threadIdx.x << 5]) < ep) {
            if (++spins > 4096) __nanosleep(32);
        }
    }
    __syncthreads();
}

// ---------------- cp.async chunk staging ----------------
__device__ __forceinline__ void stage_h(unsigned abase, int c, int d, int rp, int tid) {
    const float* hb = &d_hbuf[d][rp][0][0];
#pragma unroll
    for (int q = 0; q < 8; ++q) {
        int idx = q * 256 + tid;
        int row = idx >> 5, kq = idx & 31;
        cpa16(abase + (unsigned)(row * PIT + kq * 4) * 4u, hb + row * HH + c * 128 + kq * 4);
    }
}
__device__ __forceinline__ void stage_e(unsigned abase, int c, int d, int tid) {
    const float* eb = &d_expl[d][0][0];
    if (c < 2) {
#pragma unroll
        for (int q = 0; q < 8; ++q) {
            int idx = q * 256 + tid;
            int row = idx >> 5, kq = idx & 31;
            cpa16(abase + (unsigned)(row * PIT + kq * 4) * 4u, eb + row * 320 + c * 128 + kq * 4);
        }
    } else {
#pragma unroll
        for (int q = 0; q < 4; ++q) {
            int idx = q * 256 + tid;
            int row = idx >> 4, kq = idx & 15;
            cpa16(abase + (unsigned)(row * PIT + kq * 4) * 4u, eb + row * 320 + 256 + kq * 4);
        }
    }
}

// ---------------- MMA over one staged chunk ----------------
template <int KS>
__device__ __forceinline__ void mma_chunk(const float* A, const float* Bq, int kbase,
    float* d0, float* d1, float* dL, int am, int t4, int g0, int gid, bool ng0, bool logits)
{
#pragma unroll
    for (int ks = 0; ks < KS; ++ks) {
        int ka = ks * 8 + t4;
        unsigned a0 = __float_as_uint(A[am + ka]);
        unsigned a1 = __float_as_uint(A[am + 8 * PIT + ka]);
        unsigned a2 = __float_as_uint(A[am + ka + 4]);
        unsigned a3 = __float_as_uint(A[am + 8 * PIT + ka + 4]);
        const float* B0 = Bq + (kbase + ka) * 40;
        unsigned b0 = __float_as_uint(B0[g0 * 8 + gid]);
        unsigned b1 = __float_as_uint(B0[160 + g0 * 8 + gid]);
        mma8(d0, a0, a1, a2, a3, b0, b1);
        unsigned b2 = __float_as_uint(B0[(g0 + 1) * 8 + gid]);
        unsigned b3 = __float_as_uint(B0[160 + (g0 + 1) * 8 + gid]);
        mma8(d1, a0, a1, a2, a3, b2, b3);
        if (logits && ng0) {
            unsigned b4 = __float_as_uint(B0[32 + gid]);
            unsigned b5 = __float_as_uint(B0[160 + 32 + gid]);
            mma8(dL, a0, a1, a2, a3, b4, b5);
        }
    }
}

// ---------------- persistent recurrence ----------------
__global__ void __launch_bounds__(256, 1) rnn_persist(
    const float* __restrict__ Whh_f, const float* __restrict__ Whh_b,
    const float* __restrict__ Mk_f,  const float* __restrict__ Mk_b,
    const int* __restrict__ lens,
    float* __restrict__ out)
{
    extern __shared__ float shm[];
    __shared__ float c_s[512];
    __shared__ float S_s[64];
    __shared__ float g_s[64 * 33];

    const int blk = blockIdx.x;
    const int d   = blk >> 6;
    const int j   = blk & 63;
    const float* Whh = d ? Whh_b : Whh_f;
    const float* Mk  = d ? Mk_b : Mk_f;

    const int tid  = threadIdx.x;
    const int w    = tid >> 5;
    const int lane = tid & 31;
    const int gid  = lane >> 2, t4 = lane & 3;
    const int mtile = w & 3, g0 = (w >> 2) * 2;
    const bool ng0 = (g0 == 0);
    const int row0 = mtile * 16 + gid, row1 = row0 + 8;
    const int am   = row0 * PIT;
    const int cA   = g0 * 512 + j * 8 + 2 * t4;

    const int s0 = (j * MS) >> 6, s1 = ((j + 1) * MS) >> 6;
    const int scnt = s1 - s0;

    const unsigned ab0 = (unsigned)__cvta_generic_to_shared(shm + BQ_F);
    const unsigned ab1 = ab0 + ABUF * 4u;
    float* A0 = shm + BQ_F;
    float* A1 = A0 + ABUF;

    // one-time: pack resident B (Whh | Pt | Mk-slots) to tf32, pitch 40
    for (int idx = tid; idx < 832 * 40; idx += 256) {
        int k = idx / 40, n = idx - k * 40;
        float v;
        if (n < 32) {
            int ncol = (n >> 3) * 512 + j * 8 + (n & 7);
            v = (k < 512) ? Whh[(size_t)ncol * HH + k] : d_Pt[d][ncol][k - 512];
        } else {
            int sl = n - 32;
            v = (k < 512 && sl < scnt) ? Mk[(size_t)(s0 + sl) * HH + k] : 0.0f;
        }
        shm[k * 40 + n] = f2tf(v);
    }
    for (int i = tid; i < 512; i += 256) c_s[i] = 0.0f;
    __syncthreads();

    float xg[8];
    {
        const float* xp = &d_Xp[d][0][0];
        float2 v;
        v = __ldcs((const float2*)(xp + (size_t)row0 * G4 + cA));       xg[0]=v.x; xg[1]=v.y;
        v = __ldcs((const float2*)(xp + (size_t)row1 * G4 + cA));       xg[2]=v.x; xg[3]=v.y;
        v = __ldcs((const float2*)(xp + (size_t)row0 * G4 + cA + 512)); xg[4]=v.x; xg[5]=v.y;
        v = __ldcs((const float2*)(xp + (size_t)row1 * G4 + cA + 512)); xg[6]=v.x; xg[7]=v.y;
    }

    unsigned ep = 0;

    for (int t = 0; t < TT; ++t) {
        const int rp = t & 1, wp = rp ^ 1;

        float aG0[4] = {xg[0], xg[1], xg[2], xg[3]};
        float aG1[4] = {xg[4], xg[5], xg[6], xg[7]};
        float aL[4]  = {0.0f, 0.0f, 0.0f, 0.0f};

        if (t > 0) {
            // ---- h part (K=512, 4 chunks of 128): gates-h + logits ----
            stage_h(ab0, 0, d, rp, tid); CPA_COMMIT();
            stage_h(ab1, 1, d, rp, tid); CPA_COMMIT();
#pragma unroll 1
            for (int c = 0; c < 4; ++c) {
                if (c < 3) cpa_wait<1>(); else cpa_wait<0>();
                __syncthreads();
                mma_chunk<16>((c & 1) ? A1 : A0, shm, c * 128,
                              aG0, aG1, aL, am, t4, g0, gid, ng0, true);
                __syncthreads();
                if (c < 2) {
                    stage_h((c & 1) ? ab1 : ab0, c + 2, d, rp, tid);
                    CPA_COMMIT();
                }
            }
            // exp + expl store (tf32-rounded) + per-block partial sums
            if (ng0) {
                float e0 = f2tf(__expf(aL[0])), e1 = f2tf(__expf(aL[1]));
                float e2 = f2tf(__expf(aL[2])), e3 = f2tf(__expf(aL[3]));
                int sl0 = 2 * t4, sl1 = sl0 + 1;
                if (sl0 >= scnt) { e0 = 0.0f; e2 = 0.0f; }
                if (sl1 >= scnt) { e1 = 0.0f; e3 = 0.0f; }
                if (sl0 < scnt) {
                    d_expl[d][row0][s0 + sl0] = e0;
                    d_expl[d][row1][s0 + sl0] = e2;
                }
                if (sl1 < scnt) {
                    d_expl[d][row0][s0 + sl1] = e1;
                    d_expl[d][row1][s0 + sl1] = e3;
                }
                float p0 = e0 + e1, p1 = e2 + e3;
                p0 += __shfl_xor_sync(0xffffffffu, p0, 1);
                p0 += __shfl_xor_sync(0xffffffffu, p0, 2);
                p1 += __shfl_xor_sync(0xffffffffu, p1, 1);
                p1 += __shfl_xor_sync(0xffffffffu, p1, 2);
                if (t4 == 0) {
                    d_part[d][j][row0] = p0;
                    d_part[d][j][row1] = p1;
                }
            }
            flagbar(++ep);

            // ---- expl part (K=320, chunks 128/128/64) ----
            stage_e(ab0, 0, d, tid); CPA_COMMIT();
            stage_e(ab1, 1, d, tid); CPA_COMMIT();
            if (tid < 64) {
                float a = 0.0f;
#pragma unroll 16
                for (int jj = 0; jj < 64; ++jj) a += __ldcg(&d_part[d][jj][tid]);
                S_s[tid] = 1.0f / a;
            }
            float aE0[4] = {0,0,0,0}, aE1[4] = {0,0,0,0};
#pragma unroll 1
            for (int c = 0; c < 3; ++c) {
                if (c < 2) cpa_wait<1>(); else cpa_wait<0>();
                __syncthreads();
                if (c < 2)
                    mma_chunk<16>((c & 1) ? A1 : A0, shm, 512 + c * 128,
                                  aE0, aE1, aL, am, t4, g0, gid, false, false);
                else
                    mma_chunk<8>(A0, shm, 512 + 256,
                                 aE0, aE1, aL, am, t4, g0, gid, false, false);
                __syncthreads();
                if (c == 0) { stage_e(ab0, 2, d, tid); CPA_COMMIT(); }
            }
            float si0 = S_s[row0], si1 = S_s[row1];
            aG0[0] += aE0[0] * si0; aG0[1] += aE0[1] * si0;
            aG0[2] += aE0[2] * si1; aG0[3] += aE0[3] * si1;
            aG1[0] += aE1[0] * si0; aG1[1] += aE1[1] * si0;
            aG1[2] += aE1[2] * si1; aG1[3] += aE1[3] * si1;
        }

        __syncthreads();
        {
            int cl0 = g0 * 8 + 2 * t4, cl1 = cl0 + 8;
            g_s[row0 * 33 + cl0] = aG0[0]; g_s[row0 * 33 + cl0 + 1] = aG0[1];
            g_s[row1 * 33 + cl0] = aG0[2]; g_s[row1 * 33 + cl0 + 1] = aG0[3];
            g_s[row0 * 33 + cl1] = aG1[0]; g_s[row0 * 33 + cl1 + 1] = aG1[1];
            g_s[row1 * 33 + cl1] = aG1[2]; g_s[row1 * 33 + cl1 + 1] = aG1[3];
        }
        __syncthreads();

#pragma unroll
        for (int pi = 0; pi < 2; ++pi) {
            int p = tid + pi * 256;
            int b = p >> 3, uu = p & 7;
            float gi = g_s[b * 33 + uu];
            float gf = g_s[b * 33 + 8 + uu];
            float gg = g_s[b * 33 + 16 + uu];
            float go = g_s[b * 33 + 24 + uu];
            float iv = 1.0f / (1.0f + __expf(-gi));
            float fv = 1.0f / (1.0f + __expf(-gf));
            float gv = tanhf(gg);
            float ov = 1.0f / (1.0f + __expf(-go));
            float c = fv * c_s[p] + iv * gv;
            c_s[p] = c;
            float h = f2tf(ov * tanhf(c));          // tf32-rounded at producer
            d_hbuf[d][wp][b][j * 8 + uu] = h;
            int torig = d ? (TT - 1 - t) : t;
            float mval = (torig < lens[b]) ? h : 0.0f;
            out[((size_t)b * TT + torig) * 1024 + d * 512 + j * 8 + uu] = mval;
        }

        {
            int tn = (t + 1 < TT) ? (t + 1) : t;
            const float* xp = &d_Xp[d][(size_t)tn * BB][0];
            float2 v;
            v = __ldcs((const float2*)(xp + (size_t)row0 * G4 + cA));       xg[0]=v.x; xg[1]=v.y;
            v = __ldcs((const float2*)(xp + (size_t)row1 * G4 + cA));       xg[2]=v.x; xg[3]=v.y;
            v = __ldcs((const float2*)(xp + (size_t)row0 * G4 + cA + 512)); xg[4]=v.x; xg[5]=v.y;
            v = __ldcs((const float2*)(xp + (size_t)row1 * G4 + cA + 512)); xg[6]=v.x; xg[7]=v.y;
        }
        flagbar(++ep);
    }
}

// ---------------- launch ----------------
extern "C" void kernel_launch(void* const* d_in, const int* in_sizes, int n_in,
                              void* d_out, int out_size) {
    const float* seqs   = (const float*)d_in[0];
    const int*   ln     = (const int*)d_in[1];
    const float* Wih_f  = (const float*)d_in[2];
    const float* Whh_f  = (const float*)d_in[3];
    const float* bih_f  = (const float*)d_in[4];
    const float* bhh_f  = (const float*)d_in[5];
    const float* Mk_f   = (const float*)d_in[6];
    const float* Mv_f   = (const float*)d_in[7];
    const float* Wih_b  = (const float*)d_in[8];
    const float* Whh_b  = (const float*)d_in[9];
    const float* bih_b  = (const float*)d_in[10];
    const float* bhh_b  = (const float*)d_in[11];
    const float* Mk_b   = (const float*)d_in[12];
    const float* Mv_b   = (const float*)d_in[13];
    float* out = (float*)d_out;

    cudaFuncSetAttribute(rnn_persist,
                         cudaFuncAttributeMaxDynamicSharedMemorySize, DYN_BYTES);
    cudaFuncSetAttribute(xproj_mma,
                         cudaFuncAttributeMaxDynamicSharedMemorySize, XP_SMEM);

    reset_kernel<<<64, 256>>>();
    xproj_mma<<<dim3(32, 256, 2), 256, XP_SMEM>>>(seqs, Wih_f, Wih_b,
                                                  bih_f, bhh_f, bih_b, bhh_b);
    p_kernel<<<dim3(5, 32, 2), 256>>>(Wih_f, Wih_b, Mv_f, Mv_b);
    rnn_persist<<<NBLK, 256, DYN_BYTES>>>(Whh_f, Whh_b, Mk_f, Mk_b, ln, out);
}

// round 11
// speedup vs baseline: 5.2175x; 1.0881x over previous
#include <cuda_runtime.h>

#define TT   512
#define BB   64
#define HH   512
#define G4   2048
#define MS   300
#define INW  812
#define NBLK 128
#define BQ_F 33280              /* 832 k x 40 n resident weight smem (floats) */
#define PIT  132                /* A-chunk row pitch (floats)                 */
#define ABUF (64*PIT)           /* floats per A chunk buffer                  */
#define DYN_BYTES ((BQ_F + 2*ABUF)*4)

#define XAP  36
#define XBP  72
#define XAS  (128*XAP)
#define XBS  (32*XBP)
#define XP_SMEM ((2*XAS + 2*XBS)*4)

// ---------------- device scratch ----------------
__device__ float d_Xp[2][TT * BB][G4];
__device__ float d_hbuf[2][2][BB][HH];      // h, tf32-rounded at producer
__device__ float d_expl[2][BB][320];        // exp(logits), batch-major, tf32, zero-padded
__device__ float d_Pt[2][G4][320];
__device__ unsigned d_flag[NBLK * 32];      // per-block epoch flags, 128B apart

__global__ void reset_kernel() {
    int i = blockIdx.x * blockDim.x + threadIdx.x;
    int n = gridDim.x * blockDim.x;
    for (int x = i; x < NBLK * 32; x += n) d_flag[x] = 0u;
    float* e = &d_expl[0][0][0];
    for (int x = i; x < 2 * BB * 320; x += n) e[x] = 0.0f;
}

__device__ __forceinline__ float f2tf(float f) {
    unsigned u; asm("cvt.rna.tf32.f32 %0, %1;" : "=r"(u) : "f"(f));
    return __uint_as_float(u);
}
__device__ __forceinline__ void mma8(float* d, unsigned a0, unsigned a1,
    unsigned a2, unsigned a3, unsigned b0, unsigned b1) {
    asm volatile("mma.sync.aligned.m16n8k8.row.col.f32.tf32.tf32.f32 "
        "{%0,%1,%2,%3},{%4,%5,%6,%7},{%8,%9},{%0,%1,%2,%3};"
        : "+f"(d[0]), "+f"(d[1]), "+f"(d[2]), "+f"(d[3])
        : "r"(a0), "r"(a1), "r"(a2), "r"(a3), "r"(b0), "r"(b1));
}
__device__ __forceinline__ void cpa16(unsigned dst, const void* src) {
    asm volatile("cp.async.cg.shared.global [%0], [%1], 16;" :: "r"(dst), "l"(src));
}
#define CPA_COMMIT() asm volatile("cp.async.commit_group;")
template <int N> __device__ __forceinline__ void cpa_wait() {
    asm volatile("cp.async.wait_group %0;" :: "n"(N));
}
__device__ __forceinline__ unsigned ld_acq(const unsigned* p) {
    unsigned v;
    asm volatile("ld.acquire.gpu.global.u32 %0, [%1];" : "=r"(v) : "l"(p));
    return v;
}

// ---------------- xproj via tf32 MMA (unchanged) ----------------
__global__ void __launch_bounds__(256, 1) xproj_mma(
    const float* __restrict__ seqs,
    const float* __restrict__ Wih_f, const float* __restrict__ Wih_b,
    const float* __restrict__ bih_f, const float* __restrict__ bhh_f,
    const float* __restrict__ bih_b, const float* __restrict__ bhh_b)
{
    extern __shared__ float xs[];
    float* As = xs;
    float* Bs = xs + 2 * XAS;

    const int d  = blockIdx.z;
    const float* W  = d ? Wih_b : Wih_f;
    const float* bi = d ? bih_b : bih_f;
    const float* bh = d ? bhh_b : bhh_f;
    const int n0 = blockIdx.x * 64;
    const int m0 = blockIdx.y * 128;

    const int tid  = threadIdx.x;
    const int w    = tid >> 5, lane = tid & 31;
    const int gid  = lane >> 2, t4 = lane & 3;
    const int wm   = w & 3, wn = w >> 2;

    const int ar = tid >> 1;
    const int ak = (tid & 1) * 16;
    const int grow = m0 + ar;
    const int att  = grow >> 6;
    const int abb  = grow & 63;
    const int tsrc = d ? (TT - 1 - att) : att;
    const float* aptr = seqs + ((size_t)abb * TT + tsrc) * HH + ak;

    const int bn = tid >> 2;
    const int bk = (tid & 3) * 4;
    const float* bptr = W + (size_t)(n0 + bn) * INW + bk;

    float acc[2][4][4];
#pragma unroll
    for (int mt = 0; mt < 2; ++mt)
#pragma unroll
        for (int nt = 0; nt < 4; ++nt)
#pragma unroll
            for (int i = 0; i < 4; ++i) acc[mt][nt][i] = 0.0f;

    float4 av[4], bv[2];
#pragma unroll
    for (int q = 0; q < 4; ++q) av[q] = *(const float4*)(aptr + q * 4);
    bv[0] = *(const float4*)(bptr);
    bv[1] = *(const float4*)(bptr + 16);
    {
        float* A0 = As; float* B0 = Bs;
#pragma unroll
        for (int q = 0; q < 4; ++q) {
            float4 sv;
            sv.x = f2tf(av[q].x); sv.y = f2tf(av[q].y);
            sv.z = f2tf(av[q].z); sv.w = f2tf(av[q].w);
            *(float4*)(A0 + ar * XAP + ak + q * 4) = sv;
        }
        B0[(bk + 0) * XBP + bn] = f2tf(bv[0].x);
        B0[(bk + 1) * XBP + bn] = f2tf(bv[0].y);
        B0[(bk + 2) * XBP + bn] = f2tf(bv[0].z);
        B0[(bk + 3) * XBP + bn] = f2tf(bv[0].w);
        B0[(16 + bk + 0) * XBP + bn] = f2tf(bv[1].x);
        B0[(16 + bk + 1) * XBP + bn] = f2tf(bv[1].y);
        B0[(16 + bk + 2) * XBP + bn] = f2tf(bv[1].z);
        B0[(16 + bk + 3) * XBP + bn] = f2tf(bv[1].w);
    }
    __syncthreads();

#pragma unroll 1
    for (int kt = 0; kt < 16; ++kt) {
        if (kt < 15) {
            int k0 = (kt + 1) * 32;
#pragma unroll
            for (int q = 0; q < 4; ++q) av[q] = *(const float4*)(aptr + k0 + q * 4);
            bv[0] = *(const float4*)(bptr + k0);
            bv[1] = *(const float4*)(bptr + k0 + 16);
        }
        const float* A = As + (kt & 1) * XAS;
        const float* B = Bs + (kt & 1) * XBS;
#pragma unroll
        for (int ks = 0; ks < 4; ++ks) {
            int ka = ks * 8 + t4;
#pragma unroll
            for (int mt = 0; mt < 2; ++mt) {
                int base = (wm * 32 + mt * 16 + gid) * XAP + ka;
                unsigned a0 = __float_as_uint(A[base]);
                unsigned a1 = __float_as_uint(A[base + 8 * XAP]);
                unsigned a2 = __float_as_uint(A[base + 4]);
                unsigned a3 = __float_as_uint(A[base + 8 * XAP + 4]);
#pragma unroll
                for (int nt = 0; nt < 4; ++nt) {
                    unsigned b0 = __float_as_uint(B[ka * XBP + wn * 32 + nt * 8 + gid]);
                    unsigned b1 = __float_as_uint(B[(ka + 4) * XBP + wn * 32 + nt * 8 + gid]);
                    mma8(acc[mt][nt], a0, a1, a2, a3, b0, b1);
                }
            }
        }
        __syncthreads();
        if (kt < 15) {
            float* A1 = As + ((kt + 1) & 1) * XAS;
            float* B1 = Bs + ((kt + 1) & 1) * XBS;
#pragma unroll
            for (int q = 0; q < 4; ++q) {
                float4 sv;
                sv.x = f2tf(av[q].x); sv.y = f2tf(av[q].y);
                sv.z = f2tf(av[q].z); sv.w = f2tf(av[q].w);
                *(float4*)(A1 + ar * XAP + ak + q * 4) = sv;
            }
            B1[(bk + 0) * XBP + bn] = f2tf(bv[0].x);
            B1[(bk + 1) * XBP + bn] = f2tf(bv[0].y);
            B1[(bk + 2) * XBP + bn] = f2tf(bv[0].z);
            B1[(bk + 3) * XBP + bn] = f2tf(bv[0].w);
            B1[(16 + bk + 0) * XBP + bn] = f2tf(bv[1].x);
            B1[(16 + bk + 1) * XBP + bn] = f2tf(bv[1].y);
            B1[(16 + bk + 2) * XBP + bn] = f2tf(bv[1].z);
            B1[(16 + bk + 3) * XBP + bn] = f2tf(bv[1].w);
            __syncthreads();
        }
    }

#pragma unroll
    for (int nt = 0; nt < 4; ++nt) {
        int col = n0 + wn * 32 + nt * 8 + 2 * t4;
        float b0 = bi[col] + bh[col];
        float b1 = bi[col + 1] + bh[col + 1];
#pragma unroll
        for (int mt = 0; mt < 2; ++mt) {
            int r0 = m0 + wm * 32 + mt * 16 + gid;
            float2 v0 = {acc[mt][nt][0] + b0, acc[mt][nt][1] + b1};
            float2 v1 = {acc[mt][nt][2] + b0, acc[mt][nt][3] + b1};
            *(float2*)&d_Xp[d][r0][col]     = v0;
            *(float2*)&d_Xp[d][r0 + 8][col] = v1;
        }
    }
}

// ---------------- Pt precompute (unchanged) ----------------
__global__ void __launch_bounds__(256, 2) p_kernel(
    const float* __restrict__ Wih_f, const float* __restrict__ Wih_b,
    const float* __restrict__ Mv_f,  const float* __restrict__ Mv_b)
{
    const int d = blockIdx.z;
    const float* W  = d ? Wih_b : Wih_f;
    const float* Mv = d ? Mv_b : Mv_f;
    const int n0 = blockIdx.x * 64;
    const int m0 = blockIdx.y * 64;

    __shared__ float As[8][68], Bs[8][68];
    const int tid = threadIdx.x;
    const int ty = tid >> 4, tx = tid & 15;

    float acc[4][4];
#pragma unroll
    for (int r = 0; r < 4; ++r)
#pragma unroll
        for (int c = 0; c < 4; ++c) acc[r][c] = 0.0f;

    for (int k0 = 0; k0 < 304; k0 += 8) {
        __syncthreads();
#pragma unroll
        for (int i = 0; i < 2; ++i) {
            int idx = i * 256 + tid;
            int r = idx & 63, kk = idx >> 6;
            int k = k0 + kk;
            As[kk][r] = (k < MS) ? W[(size_t)(m0 + r) * INW + 512 + k] : 0.0f;
            Bs[kk][r] = (k < MS && n0 + r < MS) ? Mv[(size_t)k * MS + n0 + r] : 0.0f;
        }
        __syncthreads();
#pragma unroll
        for (int kk = 0; kk < 8; ++kk) {
            float a[4], b[4];
#pragma unroll
            for (int r = 0; r < 4; ++r) a[r] = As[kk][ty * 4 + r];
#pragma unroll
            for (int c = 0; c < 4; ++c) b[c] = Bs[kk][tx * 4 + c];
#pragma unroll
            for (int r = 0; r < 4; ++r)
#pragma unroll
                for (int c = 0; c < 4; ++c) acc[r][c] += a[r] * b[c];
        }
    }
#pragma unroll
    for (int r = 0; r < 4; ++r)
#pragma unroll
        for (int c = 0; c < 4; ++c)
            d_Pt[d][m0 + ty * 4 + r][n0 + tx * 4 + c] = acc[r][c];
}

// ---------------- per-direction distributed-flag barrier ----------------
__device__ __forceinline__ void flagbar(unsigned ep, int dbase) {
    __syncthreads();
    if (threadIdx.x == 0) {
        __threadfence();
        atomicExch(&d_flag[blockIdx.x << 5], ep);
    }
    if (threadIdx.x < 64) {
        int spins = 0;
        while (ld_acq(&d_flag[(dbase + threadIdx.x) << 5]) < ep) {
            if (++spins > 4096) __nanosleep(32);
        }
    }
    __syncthreads();
}

// ---------------- cp.async chunk staging ----------------
__device__ __forceinline__ void stage_h(unsigned abase, int c, int d, int rp, int tid) {
    const float* hb = &d_hbuf[d][rp][0][0];
#pragma unroll
    for (int q = 0; q < 8; ++q) {
        int idx = q * 256 + tid;
        int row = idx >> 5, kq = idx & 31;
        cpa16(abase + (unsigned)(row * PIT + kq * 4) * 4u, hb + row * HH + c * 128 + kq * 4);
    }
}
__device__ __forceinline__ void stage_e(unsigned abase, int c, int d, int tid) {
    const float* eb = &d_expl[d][0][0];
    if (c < 2) {
#pragma unroll
        for (int q = 0; q < 8; ++q) {
            int idx = q * 256 + tid;
            int row = idx >> 5, kq = idx & 31;
            cpa16(abase + (unsigned)(row * PIT + kq * 4) * 4u, eb + row * 320 + c * 128 + kq * 4);
        }
    } else {
#pragma unroll
        for (int q = 0; q < 4; ++q) {
            int idx = q * 256 + tid;
            int row = idx >> 4, kq = idx & 15;
            cpa16(abase + (unsigned)(row * PIT + kq * 4) * 4u, eb + row * 320 + 256 + kq * 4);
        }
    }
}

// ---------------- MMA over one staged chunk ----------------
template <int KS>
__device__ __forceinline__ void mma_chunk(const float* A, const float* Bq, int kbase,
    float* d0, float* d1, float* dL, int am, int t4, int g0, int gid, bool ng0, bool aux)
{
#pragma unroll
    for (int ks = 0; ks < KS; ++ks) {
        int ka = ks * 8 + t4;
        unsigned a0 = __float_as_uint(A[am + ka]);
        unsigned a1 = __float_as_uint(A[am + 8 * PIT + ka]);
        unsigned a2 = __float_as_uint(A[am + ka + 4]);
        unsigned a3 = __float_as_uint(A[am + 8 * PIT + ka + 4]);
        const float* B0 = Bq + (kbase + ka) * 40;
        unsigned b0 = __float_as_uint(B0[g0 * 8 + gid]);
        unsigned b1 = __float_as_uint(B0[160 + g0 * 8 + gid]);
        mma8(d0, a0, a1, a2, a3, b0, b1);
        unsigned b2 = __float_as_uint(B0[(g0 + 1) * 8 + gid]);
        unsigned b3 = __float_as_uint(B0[160 + (g0 + 1) * 8 + gid]);
        mma8(d1, a0, a1, a2, a3, b2, b3);
        if (aux && ng0) {
            unsigned b4 = __float_as_uint(B0[32 + gid]);
            unsigned b5 = __float_as_uint(B0[160 + 32 + gid]);
            mma8(dL, a0, a1, a2, a3, b4, b5);
        }
    }
}

// ---------------- persistent recurrence ----------------
__global__ void __launch_bounds__(256, 1) rnn_persist(
    const float* __restrict__ Whh_f, const float* __restrict__ Whh_b,
    const float* __restrict__ Mk_f,  const float* __restrict__ Mk_b,
    const int* __restrict__ lens,
    float* __restrict__ out)
{
    extern __shared__ float shm[];
    __shared__ float c_s[512];
    __shared__ float S_s[64];
    __shared__ float g_s[64 * 33];

    const int blk = blockIdx.x;
    const int d   = blk >> 6;
    const int j   = blk & 63;
    const int dbase = d << 6;
    const float* Whh = d ? Whh_b : Whh_f;
    const float* Mk  = d ? Mk_b : Mk_f;

    const int tid  = threadIdx.x;
    const int w    = tid >> 5;
    const int lane = tid & 31;
    const int gid  = lane >> 2, t4 = lane & 3;
    const int mtile = w & 3, g0 = (w >> 2) * 2;
    const bool ng0 = (g0 == 0);
    const int row0 = mtile * 16 + gid, row1 = row0 + 8;
    const int am   = row0 * PIT;
    const int cA   = g0 * 512 + j * 8 + 2 * t4;

    const int s0 = (j * MS) >> 6, s1 = ((j + 1) * MS) >> 6;
    const int scnt = s1 - s0;

    const unsigned ab0 = (unsigned)__cvta_generic_to_shared(shm + BQ_F);
    const unsigned ab1 = ab0 + ABUF * 4u;
    float* A0 = shm + BQ_F;
    float* A1 = A0 + ABUF;

    // one-time: pack resident B to tf32, pitch 40.
    // cols 0-31: Whh (k<512) | Pt (k>=512).  cols 32-39:
    //   k<512  -> Mk slots (logits);  k>=512 -> 1.0 (softmax-sum column).
    for (int idx = tid; idx < 832 * 40; idx += 256) {
        int k = idx / 40, n = idx - k * 40;
        float v;
        if (n < 32) {
            int ncol = (n >> 3) * 512 + j * 8 + (n & 7);
            v = (k < 512) ? Whh[(size_t)ncol * HH + k] : d_Pt[d][ncol][k - 512];
        } else {
            int sl = n - 32;
            if (k < 512) v = (sl < scnt) ? Mk[(size_t)(s0 + sl) * HH + k] : 0.0f;
            else         v = 1.0f;
        }
        shm[k * 40 + n] = f2tf(v);
    }
    for (int i = tid; i < 512; i += 256) c_s[i] = 0.0f;
    __syncthreads();

    float xg[8];
    {
        const float* xp = &d_Xp[d][0][0];
        float2 v;
        v = __ldcs((const float2*)(xp + (size_t)row0 * G4 + cA));       xg[0]=v.x; xg[1]=v.y;
        v = __ldcs((const float2*)(xp + (size_t)row1 * G4 + cA));       xg[2]=v.x; xg[3]=v.y;
        v = __ldcs((const float2*)(xp + (size_t)row0 * G4 + cA + 512)); xg[4]=v.x; xg[5]=v.y;
        v = __ldcs((const float2*)(xp + (size_t)row1 * G4 + cA + 512)); xg[6]=v.x; xg[7]=v.y;
    }

    unsigned ep = 0;

    for (int t = 0; t < TT; ++t) {
        const int rp = t & 1, wp = rp ^ 1;

        float aG0[4] = {xg[0], xg[1], xg[2], xg[3]};
        float aG1[4] = {xg[4], xg[5], xg[6], xg[7]};
        float aL[4]  = {0.0f, 0.0f, 0.0f, 0.0f};

        if (t > 0) {
            // ---- h part (K=512, 4 chunks of 128): gates-h + logits ----
            stage_h(ab0, 0, d, rp, tid); CPA_COMMIT();
            stage_h(ab1, 1, d, rp, tid); CPA_COMMIT();
#pragma unroll 1
            for (int c = 0; c < 4; ++c) {
                if (c < 3) cpa_wait<1>(); else cpa_wait<0>();
                __syncthreads();
                mma_chunk<16>((c & 1) ? A1 : A0, shm, c * 128,
                              aG0, aG1, aL, am, t4, g0, gid, ng0, true);
                if (c < 2) {
                    __syncthreads();
                    stage_h((c & 1) ? ab1 : ab0, c + 2, d, rp, tid);
                    CPA_COMMIT();
                }
            }
            // exp + expl store (tf32-rounded)
            if (ng0) {
                float e0 = f2tf(__expf(aL[0])), e1 = f2tf(__expf(aL[1]));
                float e2 = f2tf(__expf(aL[2])), e3 = f2tf(__expf(aL[3]));
                int sl0 = 2 * t4, sl1 = sl0 + 1;
                if (sl0 < scnt) {
                    d_expl[d][row0][s0 + sl0] = e0;
                    d_expl[d][row1][s0 + sl0] = e2;
                }
                if (sl1 < scnt) {
                    d_expl[d][row0][s0 + sl1] = e1;
                    d_expl[d][row1][s0 + sl1] = e3;
                }
            }
            flagbar(++ep, dbase);

            // ---- expl part (K=320, chunks 128/128/64); SL = row sums ----
            stage_e(ab0, 0, d, tid); CPA_COMMIT();
            stage_e(ab1, 1, d, tid); CPA_COMMIT();
            float aE0[4] = {0,0,0,0}, aE1[4] = {0,0,0,0};
            float SL[4]  = {0,0,0,0};
#pragma unroll 1
            for (int c = 0; c < 3; ++c) {
                if (c < 2) cpa_wait<1>(); else cpa_wait<0>();
                __syncthreads();
                if (c < 2)
                    mma_chunk<16>((c & 1) ? A1 : A0, shm, 512 + c * 128,
                                  aE0, aE1, SL, am, t4, g0, gid, ng0, true);
                else
                    mma_chunk<8>(A0, shm, 512 + 256,
                                 aE0, aE1, SL, am, t4, g0, gid, ng0, true);
                if (c == 0) {
                    __syncthreads();
                    stage_e(ab0, 2, d, tid); CPA_COMMIT();
                }
            }
            // warps 0-3 own rows 0-63: publish 1/S
            if (ng0 && t4 == 0) {
                S_s[row0] = 1.0f / SL[0];
                S_s[row1] = 1.0f / SL[2];
            }
            __syncthreads();
            float si0 = S_s[row0], si1 = S_s[row1];
            aG0[0] += aE0[0] * si0; aG0[1] += aE0[1] * si0;
            aG0[2] += aE0[2] * si1; aG0[3] += aE0[3] * si1;
            aG1[0] += aE1[0] * si0; aG1[1] += aE1[1] * si0;
            aG1[2] += aE1[2] * si1; aG1[3] += aE1[3] * si1;
        }

        __syncthreads();
        {
            int cl0 = g0 * 8 + 2 * t4, cl1 = cl0 + 8;
            g_s[row0 * 33 + cl0] = aG0[0]; g_s[row0 * 33 + cl0 + 1] = aG0[1];
            g_s[row1 * 33 + cl0] = aG0[2]; g_s[row1 * 33 + cl0 + 1] = aG0[3];
            g_s[row0 * 33 + cl1] = aG1[0]; g_s[row0 * 33 + cl1 + 1] = aG1[1];
            g_s[row1 * 33 + cl1] = aG1[2]; g_s[row1 * 33 + cl1 + 1] = aG1[3];
        }
        __syncthreads();

#pragma unroll
        for (int pi = 0; pi < 2; ++pi) {
            int p = tid + pi * 256;
            int b = p >> 3, uu = p & 7;
            float gi = g_s[b * 33 + uu];
            float gf = g_s[b * 33 + 8 + uu];
            float gg = g_s[b * 33 + 16 + uu];
            float go = g_s[b * 33 + 24 + uu];
            float iv = 1.0f / (1.0f + __expf(-gi));
            float fv = 1.0f / (1.0f + __expf(-gf));
            float gv = tanhf(gg);
            float ov = 1.0f / (1.0f + __expf(-go));
            float c = fv * c_s[p] + iv * gv;
            c_s[p] = c;
            float h = f2tf(ov * tanhf(c));
            d_hbuf[d][wp][b][j * 8 + uu] = h;
            int torig = d ? (TT - 1 - t) : t;
            float mval = (torig < lens[b]) ? h : 0.0f;
            out[((size_t)b * TT + torig) * 1024 + d * 512 + j * 8 + uu] = mval;
        }

        {
            int tn = (t + 1 < TT) ? (t + 1) : t;
            const float* xp = &d_Xp[d][(size_t)tn * BB][0];
            float2 v;
            v = __ldcs((const float2*)(xp + (size_t)row0 * G4 + cA));       xg[0]=v.x; xg[1]=v.y;
            v = __ldcs((const float2*)(xp + (size_t)row1 * G4 + cA));       xg[2]=v.x; xg[3]=v.y;
            v = __ldcs((const float2*)(xp + (size_t)row0 * G4 + cA + 512)); xg[4]=v.x; xg[5]=v.y;
            v = __ldcs((const float2*)(xp + (size_t)row1 * G4 + cA + 512)); xg[6]=v.x; xg[7]=v.y;
        }
        flagbar(++ep, dbase);
    }
}

// ---------------- launch ----------------
extern "C" void kernel_launch(void* const* d_in, const int* in_sizes, int n_in,
                              void* d_out, int out_size) {
    const float* seqs   = (const float*)d_in[0];
    const int*   ln     = (const int*)d_in[1];
    const float* Wih_f  = (const float*)d_in[2];
    const float* Whh_f  = (const float*)d_in[3];
    const float* bih_f  = (const float*)d_in[4];
    const float* bhh_f  = (const float*)d_in[5];
    const float* Mk_f   = (const float*)d_in[6];
    const float* Mv_f   = (const float*)d_in[7];
    const float* Wih_b  = (const float*)d_in[8];
    const float* Whh_b  = (const float*)d_in[9];
    const float* bih_b  = (const float*)d_in[10];
    const float* bhh_b  = (const float*)d_in[11];
    const float* Mk_b   = (const float*)d_in[12];
    const float* Mv_b   = (const float*)d_in[13];
    float* out = (float*)d_out;

    cudaFuncSetAttribute(rnn_persist,
                         cudaFuncAttributeMaxDynamicSharedMemorySize, DYN_BYTES);
    cudaFuncSetAttribute(xproj_mma,
                         cudaFuncAttributeMaxDynamicSharedMemorySize, XP_SMEM);

    reset_kernel<<<64, 256>>>();
    xproj_mma<<<dim3(32, 256, 2), 256, XP_SMEM>>>(seqs, Wih_f, Wih_b,
                                                  bih_f, bhh_f, bih_b, bhh_b);
    p_kernel<<<dim3(5, 32, 2), 256>>>(Wih_f, Wih_b, Mv_f, Mv_b);
    rnn_persist<<<NBLK, 256, DYN_BYTES>>>(Whh_f, Whh_b, Mk_f, Mk_b, ln, out);
}